// round 1
// baseline (speedup 1.0000x reference)
#include <cuda_runtime.h>

// Problem constants
#define NE 8
#define DD 1024
#define FF 4096
#define GG 2048

// Scratch: hidden activations per expert (E*G*F floats = 256MB each).
// __device__ globals are the allocation-guard-safe scratch mechanism.
static __device__ float g_mid[(size_t)NE * GG * FF];
static __device__ float g_gate[(size_t)NE * GG * FF];

// ---------------------------------------------------------------------------
// Classic double-buffered SGEMM: C[M,N] = A[M,K] @ B[K,N], all row-major.
// 128x128 CTA tile, BK=16, 8x8 per thread, 256 threads.
// blockIdx.z selects the expert; per-operand element strides passed in.
// ---------------------------------------------------------------------------
constexpr int BM = 128, BN = 128, BK = 16, TM = 8, TN = 8;

__global__ __launch_bounds__(256)
void sgemm_kernel(const float* __restrict__ Ag, const float* __restrict__ Bg,
                  float* __restrict__ Cg, int M, int N, int K,
                  long long strA, long long strB, long long strC)
{
    const float* A = Ag + (long long)blockIdx.z * strA;
    const float* B = Bg + (long long)blockIdx.z * strB;
    float*       C = Cg + (long long)blockIdx.z * strC;

    // A tile stored transposed [BK][BM+4]: +4 pad keeps rows 16B-aligned for
    // LDS.128 fragment reads while breaking the 4-way write conflict.
    __shared__ float As[2][BK][BM + 4];
    __shared__ float Bs[2][BK][BN];

    const int tid = threadIdx.x;
    const int tx  = tid & 15;   // 16 threads along N
    const int ty  = tid >> 4;   // 16 threads along M

    const int rowA0 = blockIdx.y * BM;
    const int colB0 = blockIdx.x * BN;

    // Global-load assignments (float4 per load, 2 iterations each)
    const int aRow = tid >> 2;        // 0..63  (row within A tile)
    const int aCol = (tid & 3) << 2;  // 0,4,8,12 (k within tile)
    const int bRow = tid >> 5;        // 0..7   (k within tile)
    const int bCol = (tid & 31) << 2; // 0..124 (col within B tile)

    float acc[TM][TN];
    #pragma unroll
    for (int i = 0; i < TM; i++)
        #pragma unroll
        for (int j = 0; j < TN; j++) acc[i][j] = 0.f;

    const int nk = K / BK;   // K is always a multiple of 16 here

    // --- prologue: load tile 0 directly to smem ---
    #pragma unroll
    for (int i = 0; i < 2; i++) {
        int r = aRow + i * 64;
        float4 va = *reinterpret_cast<const float4*>(&A[(size_t)(rowA0 + r) * K + aCol]);
        As[0][aCol + 0][r] = va.x;
        As[0][aCol + 1][r] = va.y;
        As[0][aCol + 2][r] = va.z;
        As[0][aCol + 3][r] = va.w;
    }
    #pragma unroll
    for (int i = 0; i < 2; i++) {
        int r = bRow + i * 8;
        *reinterpret_cast<float4*>(&Bs[0][r][bCol]) =
            *reinterpret_cast<const float4*>(&B[(size_t)r * N + colB0 + bCol]);
    }
    __syncthreads();

    for (int kt = 0; kt < nk; kt++) {
        const int buf  = kt & 1;
        const bool has_next = (kt + 1 < nk);

        // Stage next tile gmem -> registers FIRST so LDG latency overlaps FFMAs.
        float4 stA0, stA1, stB0, stB1;
        if (has_next) {
            const int k0 = (kt + 1) * BK;
            stA0 = *reinterpret_cast<const float4*>(&A[(size_t)(rowA0 + aRow) * K + k0 + aCol]);
            stA1 = *reinterpret_cast<const float4*>(&A[(size_t)(rowA0 + aRow + 64) * K + k0 + aCol]);
            stB0 = *reinterpret_cast<const float4*>(&B[(size_t)(k0 + bRow) * N + colB0 + bCol]);
            stB1 = *reinterpret_cast<const float4*>(&B[(size_t)(k0 + bRow + 8) * N + colB0 + bCol]);
        }

        // --- compute on current buffer ---
        #pragma unroll
        for (int k = 0; k < BK; k++) {
            float a[TM], b[TN];
            #pragma unroll
            for (int i = 0; i < TM; i += 4) {
                float4 v = *reinterpret_cast<const float4*>(&As[buf][k][ty * TM + i]);
                a[i] = v.x; a[i+1] = v.y; a[i+2] = v.z; a[i+3] = v.w;
            }
            #pragma unroll
            for (int j = 0; j < TN; j += 4) {
                float4 v = *reinterpret_cast<const float4*>(&Bs[buf][k][tx * TN + j]);
                b[j] = v.x; b[j+1] = v.y; b[j+2] = v.z; b[j+3] = v.w;
            }
            #pragma unroll
            for (int i = 0; i < TM; i++)
                #pragma unroll
                for (int j = 0; j < TN; j++)
                    acc[i][j] = fmaf(a[i], b[j], acc[i][j]);
        }

        // --- commit staged tile to the other buffer ---
        if (has_next) {
            const int nb = buf ^ 1;
            As[nb][aCol + 0][aRow]      = stA0.x;
            As[nb][aCol + 1][aRow]      = stA0.y;
            As[nb][aCol + 2][aRow]      = stA0.z;
            As[nb][aCol + 3][aRow]      = stA0.w;
            As[nb][aCol + 0][aRow + 64] = stA1.x;
            As[nb][aCol + 1][aRow + 64] = stA1.y;
            As[nb][aCol + 2][aRow + 64] = stA1.z;
            As[nb][aCol + 3][aRow + 64] = stA1.w;
            *reinterpret_cast<float4*>(&Bs[nb][bRow][bCol])     = stB0;
            *reinterpret_cast<float4*>(&Bs[nb][bRow + 8][bCol]) = stB1;
        }
        __syncthreads();
    }

    // --- epilogue: write C (float4 stores) ---
    #pragma unroll
    for (int i = 0; i < TM; i++) {
        const size_t row = (size_t)(rowA0 + ty * TM + i);
        #pragma unroll
        for (int j = 0; j < TN; j += 4) {
            float4 v = make_float4(acc[i][j], acc[i][j+1], acc[i][j+2], acc[i][j+3]);
            *reinterpret_cast<float4*>(&C[row * N + colB0 + tx * TN + j]) = v;
        }
    }
}

// ---------------------------------------------------------------------------
// SwiGLU elementwise: mid <- silu(mid) * gate   (in place, float4 vectorized)
// ---------------------------------------------------------------------------
__global__ __launch_bounds__(256)
void swiglu_kernel(float* __restrict__ mid, const float* __restrict__ gate, size_t n4)
{
    size_t i = (size_t)blockIdx.x * blockDim.x + threadIdx.x;
    if (i >= n4) return;
    float4 m = reinterpret_cast<float4*>(mid)[i];
    float4 g = reinterpret_cast<const float4*>(gate)[i];
    m.x = m.x / (1.f + __expf(-m.x)) * g.x;
    m.y = m.y / (1.f + __expf(-m.y)) * g.y;
    m.z = m.z / (1.f + __expf(-m.z)) * g.z;
    m.w = m.w / (1.f + __expf(-m.w)) * g.w;
    reinterpret_cast<float4*>(mid)[i] = m;
}

// ---------------------------------------------------------------------------
// Launch: 3 batched GEMMs (expert in grid.z) + SwiGLU. Graph-capturable:
// kernel launches only; scratch via __device__ globals.
// ---------------------------------------------------------------------------
extern "C" void kernel_launch(void* const* d_in, const int* in_sizes, int n_in,
                              void* d_out, int out_size)
{
    const float* x    = (const float*)d_in[0];  // [E*G, D]
    const float* win  = (const float*)d_in[1];  // [E*D, F]
    const float* wsw  = (const float*)d_in[2];  // [E*D, F]
    const float* wout = (const float*)d_in[3];  // [E*F, D]
    float* out = (float*)d_out;                 // [E*G, D]

    float *mid, *gate;
    cudaGetSymbolAddress((void**)&mid,  g_mid);
    cudaGetSymbolAddress((void**)&gate, g_gate);

    const dim3 block(256);

    // GEMM 1a/1b: [G,D] @ [D,F] -> [G,F] per expert
    {
        dim3 grid(FF / BN, GG / BM, NE);
        sgemm_kernel<<<grid, block>>>(x, win, mid, GG, FF, DD,
                                      (long long)GG * DD, (long long)DD * FF,
                                      (long long)GG * FF);
        sgemm_kernel<<<grid, block>>>(x, wsw, gate, GG, FF, DD,
                                      (long long)GG * DD, (long long)DD * FF,
                                      (long long)GG * FF);
    }

    // SwiGLU: mid = silu(mid) * gate
    {
        size_t n4 = (size_t)NE * GG * FF / 4;
        swiglu_kernel<<<(unsigned)((n4 + 255) / 256), 256>>>(mid, gate, n4);
    }

    // GEMM 2: [G,F] @ [F,D] -> [G,D] per expert
    {
        dim3 grid(DD / BN, GG / BM, NE);
        sgemm_kernel<<<grid, block>>>(mid, wout, out, GG, DD, FF,
                                      (long long)GG * FF, (long long)FF * DD,
                                      (long long)GG * DD);
    }
}

// round 3
// speedup vs baseline: 2.9451x; 2.9451x over previous
#include <cuda_runtime.h>
#include <cuda_bf16.h>
#include <cstdint>

#define NE 8
#define DD 1024
#define FF 4096
#define GG 2048

// ------------------------------ scratch (allocation-guard-safe) -------------
static __device__ __nv_bfloat16 g_xhi[(size_t)NE * GG * DD];
static __device__ __nv_bfloat16 g_xlo[(size_t)NE * GG * DD];
static __device__ __nv_bfloat16 g_w1hi[(size_t)NE * FF * DD];  // w_in^T  [e][F][D]
static __device__ __nv_bfloat16 g_w1lo[(size_t)NE * FF * DD];
static __device__ __nv_bfloat16 g_w2hi[(size_t)NE * FF * DD];  // w_swiglu^T
static __device__ __nv_bfloat16 g_w2lo[(size_t)NE * FF * DD];
static __device__ __nv_bfloat16 g_w3hi[(size_t)NE * DD * FF];  // w_out^T [e][D][F]
static __device__ __nv_bfloat16 g_w3lo[(size_t)NE * DD * FF];
static __device__ float         g_mid [(size_t)NE * GG * FF];
static __device__ float         g_gate[(size_t)NE * GG * FF];
static __device__ __nv_bfloat16 g_hhi [(size_t)NE * GG * FF];
static __device__ __nv_bfloat16 g_hlo [(size_t)NE * GG * FF];

// ------------------------------ helpers -------------------------------------
__device__ __forceinline__ uint32_t smem_u32(const void* p) {
    uint32_t a;
    asm("{ .reg .u64 t; cvta.to.shared.u64 t, %1; cvt.u32.u64 %0, t; }" : "=r"(a) : "l"(p));
    return a;
}

// Tile layout: 128 rows x 32 bf16 (64B/row), 16B chunks c=0..3 with XOR swizzle
// c' = c ^ ((row>>1)&3): conflict-free for ldmatrix 8-row phases AND stores.
__device__ __forceinline__ uint32_t tileoff(int row, int c) {
    return (uint32_t)((row << 6) + (((c ^ ((row >> 1) & 3))) << 4));
}

#define CP_ASYNC(dst, src) \
    asm volatile("cp.async.cg.shared.global [%0], [%1], 16;" :: "r"(dst), "l"(src) : "memory")
#define CP_COMMIT() asm volatile("cp.async.commit_group;" ::: "memory")
#define CP_WAIT0()  asm volatile("cp.async.wait_group 0;" ::: "memory")
#define CP_WAIT1()  asm volatile("cp.async.wait_group 1;" ::: "memory")

#define LDSM4(r, addr) \
    asm volatile("ldmatrix.sync.aligned.m8n8.x4.shared.b16 {%0,%1,%2,%3}, [%4];" \
                 : "=r"((r)[0]), "=r"((r)[1]), "=r"((r)[2]), "=r"((r)[3]) : "r"(addr))

#define MMA(c, a, b) \
    asm volatile("mma.sync.aligned.m16n8k16.row.col.f32.bf16.bf16.f32 " \
                 "{%0,%1,%2,%3}, {%4,%5,%6,%7}, {%8,%9}, {%0,%1,%2,%3};" \
                 : "+f"((c)[0]), "+f"((c)[1]), "+f"((c)[2]), "+f"((c)[3]) \
                 : "r"((a)[0]), "r"((a)[1]), "r"((a)[2]), "r"((a)[3]), \
                   "r"((b)[0]), "r"((b)[1]))

// ------------------------------ split-bf16 HMMA GEMM ------------------------
// C[M,N] = Ahi@Bhi^T + Ahi@Blo^T + Alo@Bhi^T ; A:[M,K], B:[N,K] (K-major bf16).
// 128x128x32 CTA tile; 8 warps 2(m)x4(n), warp tile m64xn32; cp.async 2-stage.
#define STG_B   32768   // 4 tiles x 8KB (Ahi, Alo, Bhi, Blo)
#define SMEM_GB (2 * STG_B)

__global__ __launch_bounds__(256)
void mma_gemm(const __nv_bfloat16* __restrict__ Ahi_g, const __nv_bfloat16* __restrict__ Alo_g,
              const __nv_bfloat16* __restrict__ Bhi_g, const __nv_bfloat16* __restrict__ Blo_g,
              float* __restrict__ Cg, int M, int N, int K,
              long long strA, long long strB, long long strC)
{
    extern __shared__ char smem[];
    const uint32_t sb = smem_u32(smem);
    const int tid = threadIdx.x, wid = tid >> 5, lane = tid & 31;
    const int wm = wid >> 2, wn = wid & 3;     // 2 x 4 warp grid

    const __nv_bfloat16* Ahi = Ahi_g + (long long)blockIdx.z * strA;
    const __nv_bfloat16* Alo = Alo_g + (long long)blockIdx.z * strA;
    const __nv_bfloat16* Bhi = Bhi_g + (long long)blockIdx.z * strB;
    const __nv_bfloat16* Blo = Blo_g + (long long)blockIdx.z * strB;
    float* C = Cg + (long long)blockIdx.z * strC;

    const int rowA0 = blockIdx.y * 128;
    const int colB0 = blockIdx.x * 128;

    float acc[4][4][4];
    #pragma unroll
    for (int i = 0; i < 4; i++)
        #pragma unroll
        for (int j = 0; j < 4; j++)
            #pragma unroll
            for (int k = 0; k < 4; k++) acc[i][j][k] = 0.f;

    const int ldRow = tid >> 2;        // 0..63 (x2 iters -> 128 rows... no: idx>>2)
    const int nC = K >> 5;

    auto load_stage = [&](int c, int s) {
        const uint32_t base = sb + s * STG_B;
        const int kc = c << 5;
        #pragma unroll
        for (int i = 0; i < 2; i++) {
            const int idx = tid + (i << 8);
            const int row = idx >> 2, ch = idx & 3;
            const uint32_t o = tileoff(row, ch);
            const size_t ga = (size_t)(rowA0 + row) * K + kc + ch * 8;
            const size_t gb = (size_t)(colB0 + row) * K + kc + ch * 8;
            CP_ASYNC(base + o,         Ahi + ga);
            CP_ASYNC(base + 8192 + o,  Alo + ga);
            CP_ASYNC(base + 16384 + o, Bhi + gb);
            CP_ASYNC(base + 24576 + o, Blo + gb);
        }
        CP_COMMIT();
    };
    (void)ldRow;

    load_stage(0, 0);

    for (int c = 0; c < nC; c++) {
        if (c + 1 < nC) { load_stage(c + 1, (c + 1) & 1); CP_WAIT1(); }
        else            { CP_WAIT0(); }
        __syncthreads();

        const uint32_t tb = sb + (c & 1) * STG_B;

        #pragma unroll
        for (int ks = 0; ks < 2; ks++) {
            uint32_t ah[4][4], al[4][4], bh[4][2], bl[4][2];
            const int ch = ks * 2 + (lane >> 4);
            // A fragments: 4 m16 blocks, hi + lo
            #pragma unroll
            for (int mb = 0; mb < 4; mb++) {
                const int row = wm * 64 + mb * 16 + (lane & 15);
                const uint32_t o = tileoff(row, ch);
                LDSM4(ah[mb], tb + o);
                LDSM4(al[mb], tb + 8192 + o);
            }
            // B fragments: 2 x (n16 block -> two n8 frags), hi + lo
            #pragma unroll
            for (int nb16 = 0; nb16 < 2; nb16++) {
                const int row = wn * 32 + nb16 * 16 + (lane & 15);
                const uint32_t o = tileoff(row, ch);
                uint32_t r[4];
                LDSM4(r, tb + 16384 + o);
                bh[nb16 * 2][0] = r[0]; bh[nb16 * 2][1] = r[2];
                bh[nb16 * 2 + 1][0] = r[1]; bh[nb16 * 2 + 1][1] = r[3];
                LDSM4(r, tb + 24576 + o);
                bl[nb16 * 2][0] = r[0]; bl[nb16 * 2][1] = r[2];
                bl[nb16 * 2 + 1][0] = r[1]; bl[nb16 * 2 + 1][1] = r[3];
            }
            // 3-product split MMA
            #pragma unroll
            for (int mb = 0; mb < 4; mb++)
                #pragma unroll
                for (int nb = 0; nb < 4; nb++) {
                    MMA(acc[mb][nb], ah[mb], bh[nb]);
                    MMA(acc[mb][nb], ah[mb], bl[nb]);
                    MMA(acc[mb][nb], al[mb], bh[nb]);
                }
        }
        __syncthreads();
    }

    // epilogue: fragment layout -> (m, n) float2 stores
    #pragma unroll
    for (int mb = 0; mb < 4; mb++) {
        const int m = rowA0 + wm * 64 + mb * 16 + (lane >> 2);
        #pragma unroll
        for (int nb = 0; nb < 4; nb++) {
            const int n = colB0 + wn * 32 + nb * 8 + (lane & 3) * 2;
            *reinterpret_cast<float2*>(&C[(size_t)m * N + n]) =
                make_float2(acc[mb][nb][0], acc[mb][nb][1]);
            *reinterpret_cast<float2*>(&C[(size_t)(m + 8) * N + n]) =
                make_float2(acc[mb][nb][2], acc[mb][nb][3]);
        }
    }
}

// ------------------------------ conversion kernels --------------------------
__global__ __launch_bounds__(256)
void split_f32_kernel(const float* __restrict__ in, __nv_bfloat16* __restrict__ hi,
                      __nv_bfloat16* __restrict__ lo, size_t n4)
{
    size_t i = (size_t)blockIdx.x * blockDim.x + threadIdx.x;
    if (i >= n4) return;
    float4 v = reinterpret_cast<const float4*>(in)[i];
    __nv_bfloat16 h0 = __float2bfloat16(v.x), h1 = __float2bfloat16(v.y);
    __nv_bfloat16 h2 = __float2bfloat16(v.z), h3 = __float2bfloat16(v.w);
    __nv_bfloat16 l0 = __float2bfloat16(v.x - __bfloat162float(h0));
    __nv_bfloat16 l1 = __float2bfloat16(v.y - __bfloat162float(h1));
    __nv_bfloat16 l2 = __float2bfloat16(v.z - __bfloat162float(h2));
    __nv_bfloat16 l3 = __float2bfloat16(v.w - __bfloat162float(h3));
    reinterpret_cast<ushort4*>(hi)[i] = make_ushort4(__bfloat16_as_ushort(h0), __bfloat16_as_ushort(h1),
                                                     __bfloat16_as_ushort(h2), __bfloat16_as_ushort(h3));
    reinterpret_cast<ushort4*>(lo)[i] = make_ushort4(__bfloat16_as_ushort(l0), __bfloat16_as_ushort(l1),
                                                     __bfloat16_as_ushort(l2), __bfloat16_as_ushort(l3));
}

// w [e][K][N] fp32 -> hiT/loT [e][N][K] bf16 (32x32 tiles)
__global__ __launch_bounds__(256)
void transpose_split_kernel(const float* __restrict__ w, __nv_bfloat16* __restrict__ hiT,
                            __nv_bfloat16* __restrict__ loT, int K, int N)
{
    __shared__ float t[32][33];
    const int e = blockIdx.z;
    const int n0 = blockIdx.x * 32, k0 = blockIdx.y * 32;
    const int tx = threadIdx.x, ty = threadIdx.y;   // (32, 8)
    const float* we = w + (size_t)e * K * N;
    #pragma unroll
    for (int j = 0; j < 4; j++)
        t[ty + 8 * j][tx] = we[(size_t)(k0 + ty + 8 * j) * N + n0 + tx];
    __syncthreads();
    __nv_bfloat16* ho = hiT + (size_t)e * N * K;
    __nv_bfloat16* lo = loT + (size_t)e * N * K;
    #pragma unroll
    for (int j = 0; j < 4; j++) {
        float v = t[tx][ty + 8 * j];
        __nv_bfloat16 h = __float2bfloat16(v);
        __nv_bfloat16 l = __float2bfloat16(v - __bfloat162float(h));
        const size_t o = (size_t)(n0 + ty + 8 * j) * K + k0 + tx;
        ho[o] = h; lo[o] = l;
    }
}

__global__ __launch_bounds__(256)
void swiglu_split_kernel(const float* __restrict__ mid, const float* __restrict__ gate,
                         __nv_bfloat16* __restrict__ hhi, __nv_bfloat16* __restrict__ hlo, size_t n4)
{
    size_t i = (size_t)blockIdx.x * blockDim.x + threadIdx.x;
    if (i >= n4) return;
    float4 m = reinterpret_cast<const float4*>(mid)[i];
    float4 g = reinterpret_cast<const float4*>(gate)[i];
    float h[4];
    h[0] = m.x / (1.f + __expf(-m.x)) * g.x;
    h[1] = m.y / (1.f + __expf(-m.y)) * g.y;
    h[2] = m.z / (1.f + __expf(-m.z)) * g.z;
    h[3] = m.w / (1.f + __expf(-m.w)) * g.w;
    ushort4 uh, ul;
    __nv_bfloat16 b;
    b = __float2bfloat16(h[0]); uh.x = __bfloat16_as_ushort(b); ul.x = __bfloat16_as_ushort(__float2bfloat16(h[0] - __bfloat162float(b)));
    b = __float2bfloat16(h[1]); uh.y = __bfloat16_as_ushort(b); ul.y = __bfloat16_as_ushort(__float2bfloat16(h[1] - __bfloat162float(b)));
    b = __float2bfloat16(h[2]); uh.z = __bfloat16_as_ushort(b); ul.z = __bfloat16_as_ushort(__float2bfloat16(h[2] - __bfloat162float(b)));
    b = __float2bfloat16(h[3]); uh.w = __bfloat16_as_ushort(b); ul.w = __bfloat16_as_ushort(__float2bfloat16(h[3] - __bfloat162float(b)));
    reinterpret_cast<ushort4*>(hhi)[i] = uh;
    reinterpret_cast<ushort4*>(hlo)[i] = ul;
}

// ------------------------------ launch --------------------------------------
extern "C" void kernel_launch(void* const* d_in, const int* in_sizes, int n_in,
                              void* d_out, int out_size)
{
    const float* x    = (const float*)d_in[0];
    const float* win  = (const float*)d_in[1];
    const float* wsw  = (const float*)d_in[2];
    const float* wout = (const float*)d_in[3];
    float* out = (float*)d_out;

    __nv_bfloat16 *xhi, *xlo, *w1h, *w1l, *w2h, *w2l, *w3h, *w3l, *hhi, *hlo;
    float *mid, *gate;
    cudaGetSymbolAddress((void**)&xhi, g_xhi);   cudaGetSymbolAddress((void**)&xlo, g_xlo);
    cudaGetSymbolAddress((void**)&w1h, g_w1hi);  cudaGetSymbolAddress((void**)&w1l, g_w1lo);
    cudaGetSymbolAddress((void**)&w2h, g_w2hi);  cudaGetSymbolAddress((void**)&w2l, g_w2lo);
    cudaGetSymbolAddress((void**)&w3h, g_w3hi);  cudaGetSymbolAddress((void**)&w3l, g_w3lo);
    cudaGetSymbolAddress((void**)&mid, g_mid);   cudaGetSymbolAddress((void**)&gate, g_gate);
    cudaGetSymbolAddress((void**)&hhi, g_hhi);   cudaGetSymbolAddress((void**)&hlo, g_hlo);

    cudaFuncSetAttribute(mma_gemm, cudaFuncAttributeMaxDynamicSharedMemorySize, SMEM_GB);

    // 1) split x into bf16 hi/lo
    {
        size_t n4 = (size_t)NE * GG * DD / 4;
        split_f32_kernel<<<(unsigned)((n4 + 255) / 256), 256>>>(x, xhi, xlo, n4);
    }
    // 2) transpose + split weights (to [N,K] K-major for the .col operand)
    {
        dim3 blk(32, 8);
        transpose_split_kernel<<<dim3(FF / 32, DD / 32, NE), blk>>>(win,  w1h, w1l, DD, FF);
        transpose_split_kernel<<<dim3(FF / 32, DD / 32, NE), blk>>>(wsw,  w2h, w2l, DD, FF);
        transpose_split_kernel<<<dim3(DD / 32, FF / 32, NE), blk>>>(wout, w3h, w3l, FF, DD);
    }
    // 3) GEMM1 pair: [G,D] @ [F,D]^T -> [G,F]
    {
        dim3 grid(FF / 128, GG / 128, NE);
        mma_gemm<<<grid, 256, SMEM_GB>>>(xhi, xlo, w1h, w1l, mid, GG, FF, DD,
                                         (long long)GG * DD, (long long)FF * DD, (long long)GG * FF);
        mma_gemm<<<grid, 256, SMEM_GB>>>(xhi, xlo, w2h, w2l, gate, GG, FF, DD,
                                         (long long)GG * DD, (long long)FF * DD, (long long)GG * FF);
    }
    // 4) SwiGLU -> hidden hi/lo bf16
    {
        size_t n4 = (size_t)NE * GG * FF / 4;
        swiglu_split_kernel<<<(unsigned)((n4 + 255) / 256), 256>>>(mid, gate, hhi, hlo, n4);
    }
    // 5) GEMM2: [G,F] @ [D,F]^T -> [G,D]
    {
        dim3 grid(DD / 128, GG / 128, NE);
        mma_gemm<<<grid, 256, SMEM_GB>>>(hhi, hlo, w3h, w3l, out, GG, DD, FF,
                                         (long long)GG * FF, (long long)DD * FF, (long long)GG * DD);
    }
}

// round 4
// speedup vs baseline: 3.0667x; 1.0413x over previous
#include <cuda_runtime.h>
#include <cuda_bf16.h>
#include <cstdint>

#define NE 8
#define DD 1024
#define FF 4096
#define GG 2048

// ------------------------------ scratch (allocation-guard-safe) -------------
static __device__ __nv_bfloat16 g_xhi[(size_t)NE * GG * DD];
static __device__ __nv_bfloat16 g_xlo[(size_t)NE * GG * DD];
static __device__ __nv_bfloat16 g_w1hi[(size_t)NE * FF * DD];  // w_in^T  [e][F][D]
static __device__ __nv_bfloat16 g_w1lo[(size_t)NE * FF * DD];
static __device__ __nv_bfloat16 g_w2hi[(size_t)NE * FF * DD];  // w_swiglu^T
static __device__ __nv_bfloat16 g_w2lo[(size_t)NE * FF * DD];
static __device__ __nv_bfloat16 g_w3hi[(size_t)NE * DD * FF];  // w_out^T [e][D][F]
static __device__ __nv_bfloat16 g_w3lo[(size_t)NE * DD * FF];
static __device__ __nv_bfloat16 g_hhi [(size_t)NE * GG * FF];
static __device__ __nv_bfloat16 g_hlo [(size_t)NE * GG * FF];

// ------------------------------ helpers -------------------------------------
__device__ __forceinline__ uint32_t smem_u32(const void* p) {
    uint32_t a;
    asm("{ .reg .u64 t; cvta.to.shared.u64 t, %1; cvt.u32.u64 %0, t; }" : "=r"(a) : "l"(p));
    return a;
}

// Tile row = 32 bf16 (64B), 16B chunks c=0..3, XOR swizzle c' = c ^ ((row>>1)&3):
// conflict-free for both cp.async stores and ldmatrix 8-row phases.
__device__ __forceinline__ uint32_t tileoff(int row, int c) {
    return (uint32_t)((row << 6) + (((c ^ ((row >> 1) & 3))) << 4));
}

#define CP_ASYNC(dst, src) \
    asm volatile("cp.async.cg.shared.global [%0], [%1], 16;" :: "r"(dst), "l"(src) : "memory")
#define CP_COMMIT() asm volatile("cp.async.commit_group;" ::: "memory")
#define CP_WAIT0()  asm volatile("cp.async.wait_group 0;" ::: "memory")
#define CP_WAIT1()  asm volatile("cp.async.wait_group 1;" ::: "memory")
#define CP_WAIT2()  asm volatile("cp.async.wait_group 2;" ::: "memory")

#define LDSM4(r, addr) \
    asm volatile("ldmatrix.sync.aligned.m8n8.x4.shared.b16 {%0,%1,%2,%3}, [%4];" \
                 : "=r"((r)[0]), "=r"((r)[1]), "=r"((r)[2]), "=r"((r)[3]) : "r"(addr))

#define MMA(c, a, b) \
    asm volatile("mma.sync.aligned.m16n8k16.row.col.f32.bf16.bf16.f32 " \
                 "{%0,%1,%2,%3}, {%4,%5,%6,%7}, {%8,%9}, {%0,%1,%2,%3};" \
                 : "+f"((c)[0]), "+f"((c)[1]), "+f"((c)[2]), "+f"((c)[3]) \
                 : "r"((a)[0]), "r"((a)[1]), "r"((a)[2]), "r"((a)[3]), \
                   "r"((b)[0]), "r"((b)[1]))

// ============================================================================
// Fused GEMM1-pair + SwiGLU:
//   mid  = x @ w1^T ; gate = x @ w2^T ; h = silu(mid)*gate -> hhi/hlo bf16
// CTA tile: m128 x n64, k-chunk 32, 3-stage cp.async pipeline.
// 8 warps 2(m)x4(n); warp tile m64 x n16 PER OUTPUT (two accumulator sets).
// ============================================================================
#define FSTG 32768   // Ahi(8K) Alo(8K) B1h(4K) B1l(4K) B2h(4K) B2l(4K)
#define FUSED_SMEM (3 * FSTG)

__global__ __launch_bounds__(256)
void fused_gemm1_swiglu(const __nv_bfloat16* __restrict__ Ahi_g, const __nv_bfloat16* __restrict__ Alo_g,
                        const __nv_bfloat16* __restrict__ B1h_g, const __nv_bfloat16* __restrict__ B1l_g,
                        const __nv_bfloat16* __restrict__ B2h_g, const __nv_bfloat16* __restrict__ B2l_g,
                        __nv_bfloat16* __restrict__ Hhi_g, __nv_bfloat16* __restrict__ Hlo_g)
{
    extern __shared__ char smem[];
    const uint32_t sb = smem_u32(smem);
    const int tid = threadIdx.x, wid = tid >> 5, lane = tid & 31;
    const int wm = wid >> 2, wn = wid & 3;

    const long long e = blockIdx.z;
    const __nv_bfloat16* Ahi = Ahi_g + e * (long long)GG * DD;
    const __nv_bfloat16* Alo = Alo_g + e * (long long)GG * DD;
    const __nv_bfloat16* B1h = B1h_g + e * (long long)FF * DD;
    const __nv_bfloat16* B1l = B1l_g + e * (long long)FF * DD;
    const __nv_bfloat16* B2h = B2h_g + e * (long long)FF * DD;
    const __nv_bfloat16* B2l = B2l_g + e * (long long)FF * DD;
    __nv_bfloat16* Hhi = Hhi_g + e * (long long)GG * FF;
    __nv_bfloat16* Hlo = Hlo_g + e * (long long)GG * FF;

    const int rowA0 = blockIdx.y * 128;
    const int colB0 = blockIdx.x * 64;

    float acc1[4][2][4], acc2[4][2][4];
    #pragma unroll
    for (int i = 0; i < 4; i++)
        #pragma unroll
        for (int j = 0; j < 2; j++)
            #pragma unroll
            for (int k = 0; k < 4; k++) { acc1[i][j][k] = 0.f; acc2[i][j][k] = 0.f; }

    const int nC = DD >> 5;   // 32 chunks

    auto load_stage = [&](int c, int s) {
        const uint32_t base = sb + s * FSTG;
        const int kc = c << 5;
        // A (hi+lo): 128 rows x 4 chunks, 2 slots per thread
        #pragma unroll
        for (int i = 0; i < 2; i++) {
            const int idx = tid + (i << 8);
            const int row = idx >> 2, ch = idx & 3;
            const uint32_t o = tileoff(row, ch);
            const size_t g = (size_t)(rowA0 + row) * DD + kc + ch * 8;
            CP_ASYNC(base + o,        Ahi + g);
            CP_ASYNC(base + 8192 + o, Alo + g);
        }
        // B (4 tiles): 64 rows x 4 chunks, 1 slot per thread
        {
            const int row = tid >> 2, ch = tid & 3;
            const uint32_t o = tileoff(row, ch);
            const size_t g = (size_t)(colB0 + row) * DD + kc + ch * 8;
            CP_ASYNC(base + 16384 + o, B1h + g);
            CP_ASYNC(base + 20480 + o, B1l + g);
            CP_ASYNC(base + 24576 + o, B2h + g);
            CP_ASYNC(base + 28672 + o, B2l + g);
        }
        CP_COMMIT();
    };

    load_stage(0, 0);
    load_stage(1, 1);

    int s = 0;
    for (int c = 0; c < nC; c++) {
        if (c + 2 < nC) {
            int s2 = s + 2; if (s2 >= 3) s2 -= 3;
            load_stage(c + 2, s2);
            CP_WAIT2();
        } else if (c + 1 < nC) CP_WAIT1();
        else                   CP_WAIT0();
        __syncthreads();

        const uint32_t tb = sb + s * FSTG;

        #pragma unroll
        for (int ks = 0; ks < 2; ks++) {
            const int ch = ks * 2 + (lane >> 4);
            uint32_t ah[4][4], al[4][4];
            uint32_t b1h[2][2], b1l[2][2], b2h[2][2], b2l[2][2];
            #pragma unroll
            for (int mb = 0; mb < 4; mb++) {
                const int row = wm * 64 + mb * 16 + (lane & 15);
                const uint32_t o = tileoff(row, ch);
                LDSM4(ah[mb], tb + o);
                LDSM4(al[mb], tb + 8192 + o);
            }
            {
                const int row = wn * 16 + (lane & 15);
                const uint32_t o = tileoff(row, ch);
                uint32_t r[4];
                LDSM4(r, tb + 16384 + o);
                b1h[0][0] = r[0]; b1h[0][1] = r[2]; b1h[1][0] = r[1]; b1h[1][1] = r[3];
                LDSM4(r, tb + 20480 + o);
                b1l[0][0] = r[0]; b1l[0][1] = r[2]; b1l[1][0] = r[1]; b1l[1][1] = r[3];
                LDSM4(r, tb + 24576 + o);
                b2h[0][0] = r[0]; b2h[0][1] = r[2]; b2h[1][0] = r[1]; b2h[1][1] = r[3];
                LDSM4(r, tb + 28672 + o);
                b2l[0][0] = r[0]; b2l[0][1] = r[2]; b2l[1][0] = r[1]; b2l[1][1] = r[3];
            }
            #pragma unroll
            for (int mb = 0; mb < 4; mb++)
                #pragma unroll
                for (int nb = 0; nb < 2; nb++) {
                    MMA(acc1[mb][nb], ah[mb], b1h[nb]);
                    MMA(acc1[mb][nb], ah[mb], b1l[nb]);
                    MMA(acc1[mb][nb], al[mb], b1h[nb]);
                    MMA(acc2[mb][nb], ah[mb], b2h[nb]);
                    MMA(acc2[mb][nb], ah[mb], b2l[nb]);
                    MMA(acc2[mb][nb], al[mb], b2h[nb]);
                }
        }
        __syncthreads();
        if (++s == 3) s = 0;
    }

    // epilogue: h = silu(mid)*gate, split to bf16 hi/lo, store
    #pragma unroll
    for (int mb = 0; mb < 4; mb++) {
        const int m0 = rowA0 + wm * 64 + mb * 16 + (lane >> 2);
        #pragma unroll
        for (int nb = 0; nb < 2; nb++) {
            const int n = colB0 + wn * 16 + nb * 8 + (lane & 3) * 2;
            #pragma unroll
            for (int half = 0; half < 2; half++) {
                const int m = m0 + half * 8;
                float md0 = acc1[mb][nb][half * 2 + 0], gt0 = acc2[mb][nb][half * 2 + 0];
                float md1 = acc1[mb][nb][half * 2 + 1], gt1 = acc2[mb][nb][half * 2 + 1];
                float h0 = md0 / (1.f + __expf(-md0)) * gt0;
                float h1 = md1 / (1.f + __expf(-md1)) * gt1;
                __nv_bfloat16 h0h = __float2bfloat16(h0);
                __nv_bfloat16 h1h = __float2bfloat16(h1);
                __nv_bfloat16 h0l = __float2bfloat16(h0 - __bfloat162float(h0h));
                __nv_bfloat16 h1l = __float2bfloat16(h1 - __bfloat162float(h1h));
                *reinterpret_cast<ushort2*>(&Hhi[(size_t)m * FF + n]) =
                    make_ushort2(__bfloat16_as_ushort(h0h), __bfloat16_as_ushort(h1h));
                *reinterpret_cast<ushort2*>(&Hlo[(size_t)m * FF + n]) =
                    make_ushort2(__bfloat16_as_ushort(h0l), __bfloat16_as_ushort(h1l));
            }
        }
    }
}

// ============================================================================
// Generic split-bf16 HMMA GEMM (used for GEMM2): C = Ahi@Bhi^T + Ahi@Blo^T + Alo@Bhi^T
// 128x128x32 CTA tile, 3-stage cp.async pipeline, 8 warps 2(m)x4(n), warp m64xn32.
// ============================================================================
#define GSTG 32768   // Ahi(8K) Alo(8K) Bhi(8K) Blo(8K)
#define GEMM_SMEM (3 * GSTG)

__global__ __launch_bounds__(256)
void mma_gemm(const __nv_bfloat16* __restrict__ Ahi_g, const __nv_bfloat16* __restrict__ Alo_g,
              const __nv_bfloat16* __restrict__ Bhi_g, const __nv_bfloat16* __restrict__ Blo_g,
              float* __restrict__ Cg, int M, int N, int K,
              long long strA, long long strB, long long strC)
{
    extern __shared__ char smem[];
    const uint32_t sb = smem_u32(smem);
    const int tid = threadIdx.x, wid = tid >> 5, lane = tid & 31;
    const int wm = wid >> 2, wn = wid & 3;

    const __nv_bfloat16* Ahi = Ahi_g + (long long)blockIdx.z * strA;
    const __nv_bfloat16* Alo = Alo_g + (long long)blockIdx.z * strA;
    const __nv_bfloat16* Bhi = Bhi_g + (long long)blockIdx.z * strB;
    const __nv_bfloat16* Blo = Blo_g + (long long)blockIdx.z * strB;
    float* C = Cg + (long long)blockIdx.z * strC;

    const int rowA0 = blockIdx.y * 128;
    const int colB0 = blockIdx.x * 128;

    float acc[4][4][4];
    #pragma unroll
    for (int i = 0; i < 4; i++)
        #pragma unroll
        for (int j = 0; j < 4; j++)
            #pragma unroll
            for (int k = 0; k < 4; k++) acc[i][j][k] = 0.f;

    const int nC = K >> 5;

    auto load_stage = [&](int c, int s) {
        const uint32_t base = sb + s * GSTG;
        const int kc = c << 5;
        #pragma unroll
        for (int i = 0; i < 2; i++) {
            const int idx = tid + (i << 8);
            const int row = idx >> 2, ch = idx & 3;
            const uint32_t o = tileoff(row, ch);
            const size_t ga = (size_t)(rowA0 + row) * K + kc + ch * 8;
            const size_t gb = (size_t)(colB0 + row) * K + kc + ch * 8;
            CP_ASYNC(base + o,         Ahi + ga);
            CP_ASYNC(base + 8192 + o,  Alo + ga);
            CP_ASYNC(base + 16384 + o, Bhi + gb);
            CP_ASYNC(base + 24576 + o, Blo + gb);
        }
        CP_COMMIT();
    };

    load_stage(0, 0);
    load_stage(1, 1);

    int s = 0;
    for (int c = 0; c < nC; c++) {
        if (c + 2 < nC) {
            int s2 = s + 2; if (s2 >= 3) s2 -= 3;
            load_stage(c + 2, s2);
            CP_WAIT2();
        } else if (c + 1 < nC) CP_WAIT1();
        else                   CP_WAIT0();
        __syncthreads();

        const uint32_t tb = sb + s * GSTG;

        #pragma unroll
        for (int ks = 0; ks < 2; ks++) {
            uint32_t ah[4][4], al[4][4], bh[4][2], bl[4][2];
            const int ch = ks * 2 + (lane >> 4);
            #pragma unroll
            for (int mb = 0; mb < 4; mb++) {
                const int row = wm * 64 + mb * 16 + (lane & 15);
                const uint32_t o = tileoff(row, ch);
                LDSM4(ah[mb], tb + o);
                LDSM4(al[mb], tb + 8192 + o);
            }
            #pragma unroll
            for (int nb16 = 0; nb16 < 2; nb16++) {
                const int row = wn * 32 + nb16 * 16 + (lane & 15);
                const uint32_t o = tileoff(row, ch);
                uint32_t r[4];
                LDSM4(r, tb + 16384 + o);
                bh[nb16 * 2][0] = r[0]; bh[nb16 * 2][1] = r[2];
                bh[nb16 * 2 + 1][0] = r[1]; bh[nb16 * 2 + 1][1] = r[3];
                LDSM4(r, tb + 24576 + o);
                bl[nb16 * 2][0] = r[0]; bl[nb16 * 2][1] = r[2];
                bl[nb16 * 2 + 1][0] = r[1]; bl[nb16 * 2 + 1][1] = r[3];
            }
            #pragma unroll
            for (int mb = 0; mb < 4; mb++)
                #pragma unroll
                for (int nb = 0; nb < 4; nb++) {
                    MMA(acc[mb][nb], ah[mb], bh[nb]);
                    MMA(acc[mb][nb], ah[mb], bl[nb]);
                    MMA(acc[mb][nb], al[mb], bh[nb]);
                }
        }
        __syncthreads();
        if (++s == 3) s = 0;
    }

    #pragma unroll
    for (int mb = 0; mb < 4; mb++) {
        const int m = rowA0 + wm * 64 + mb * 16 + (lane >> 2);
        #pragma unroll
        for (int nb = 0; nb < 4; nb++) {
            const int n = colB0 + wn * 32 + nb * 8 + (lane & 3) * 2;
            *reinterpret_cast<float2*>(&C[(size_t)m * N + n]) =
                make_float2(acc[mb][nb][0], acc[mb][nb][1]);
            *reinterpret_cast<float2*>(&C[(size_t)(m + 8) * N + n]) =
                make_float2(acc[mb][nb][2], acc[mb][nb][3]);
        }
    }
}

// ------------------------------ conversion kernels --------------------------
__global__ __launch_bounds__(256)
void split_f32_kernel(const float* __restrict__ in, __nv_bfloat16* __restrict__ hi,
                      __nv_bfloat16* __restrict__ lo, size_t n4)
{
    size_t i = (size_t)blockIdx.x * blockDim.x + threadIdx.x;
    if (i >= n4) return;
    float4 v = reinterpret_cast<const float4*>(in)[i];
    __nv_bfloat16 h0 = __float2bfloat16(v.x), h1 = __float2bfloat16(v.y);
    __nv_bfloat16 h2 = __float2bfloat16(v.z), h3 = __float2bfloat16(v.w);
    __nv_bfloat16 l0 = __float2bfloat16(v.x - __bfloat162float(h0));
    __nv_bfloat16 l1 = __float2bfloat16(v.y - __bfloat162float(h1));
    __nv_bfloat16 l2 = __float2bfloat16(v.z - __bfloat162float(h2));
    __nv_bfloat16 l3 = __float2bfloat16(v.w - __bfloat162float(h3));
    reinterpret_cast<ushort4*>(hi)[i] = make_ushort4(__bfloat16_as_ushort(h0), __bfloat16_as_ushort(h1),
                                                     __bfloat16_as_ushort(h2), __bfloat16_as_ushort(h3));
    reinterpret_cast<ushort4*>(lo)[i] = make_ushort4(__bfloat16_as_ushort(l0), __bfloat16_as_ushort(l1),
                                                     __bfloat16_as_ushort(l2), __bfloat16_as_ushort(l3));
}

// w [e][K][N] fp32 -> hiT/loT [e][N][K] bf16 (32x32 tiles)
__global__ __launch_bounds__(256)
void transpose_split_kernel(const float* __restrict__ w, __nv_bfloat16* __restrict__ hiT,
                            __nv_bfloat16* __restrict__ loT, int K, int N)
{
    __shared__ float t[32][33];
    const int e = blockIdx.z;
    const int n0 = blockIdx.x * 32, k0 = blockIdx.y * 32;
    const int tx = threadIdx.x, ty = threadIdx.y;   // (32, 8)
    const float* we = w + (size_t)e * K * N;
    #pragma unroll
    for (int j = 0; j < 4; j++)
        t[ty + 8 * j][tx] = we[(size_t)(k0 + ty + 8 * j) * N + n0 + tx];
    __syncthreads();
    __nv_bfloat16* ho = hiT + (size_t)e * N * K;
    __nv_bfloat16* lo = loT + (size_t)e * N * K;
    #pragma unroll
    for (int j = 0; j < 4; j++) {
        float v = t[tx][ty + 8 * j];
        __nv_bfloat16 h = __float2bfloat16(v);
        __nv_bfloat16 l = __float2bfloat16(v - __bfloat162float(h));
        const size_t o = (size_t)(n0 + ty + 8 * j) * K + k0 + tx;
        ho[o] = h; lo[o] = l;
    }
}

// ------------------------------ launch --------------------------------------
extern "C" void kernel_launch(void* const* d_in, const int* in_sizes, int n_in,
                              void* d_out, int out_size)
{
    const float* x    = (const float*)d_in[0];
    const float* win  = (const float*)d_in[1];
    const float* wsw  = (const float*)d_in[2];
    const float* wout = (const float*)d_in[3];
    float* out = (float*)d_out;

    __nv_bfloat16 *xhi, *xlo, *w1h, *w1l, *w2h, *w2l, *w3h, *w3l, *hhi, *hlo;
    cudaGetSymbolAddress((void**)&xhi, g_xhi);   cudaGetSymbolAddress((void**)&xlo, g_xlo);
    cudaGetSymbolAddress((void**)&w1h, g_w1hi);  cudaGetSymbolAddress((void**)&w1l, g_w1lo);
    cudaGetSymbolAddress((void**)&w2h, g_w2hi);  cudaGetSymbolAddress((void**)&w2l, g_w2lo);
    cudaGetSymbolAddress((void**)&w3h, g_w3hi);  cudaGetSymbolAddress((void**)&w3l, g_w3lo);
    cudaGetSymbolAddress((void**)&hhi, g_hhi);   cudaGetSymbolAddress((void**)&hlo, g_hlo);

    cudaFuncSetAttribute(fused_gemm1_swiglu, cudaFuncAttributeMaxDynamicSharedMemorySize, FUSED_SMEM);
    cudaFuncSetAttribute(mma_gemm, cudaFuncAttributeMaxDynamicSharedMemorySize, GEMM_SMEM);

    // 1) split x into bf16 hi/lo
    {
        size_t n4 = (size_t)NE * GG * DD / 4;
        split_f32_kernel<<<(unsigned)((n4 + 255) / 256), 256>>>(x, xhi, xlo, n4);
    }
    // 2) transpose + split weights (to [N,K] K-major for the .col operand)
    {
        dim3 blk(32, 8);
        transpose_split_kernel<<<dim3(FF / 32, DD / 32, NE), blk>>>(win,  w1h, w1l, DD, FF);
        transpose_split_kernel<<<dim3(FF / 32, DD / 32, NE), blk>>>(wsw,  w2h, w2l, DD, FF);
        transpose_split_kernel<<<dim3(DD / 32, FF / 32, NE), blk>>>(wout, w3h, w3l, FF, DD);
    }
    // 3) fused GEMM1 pair + SwiGLU -> hidden hi/lo bf16
    {
        dim3 grid(FF / 64, GG / 128, NE);
        fused_gemm1_swiglu<<<grid, 256, FUSED_SMEM>>>(xhi, xlo, w1h, w1l, w2h, w2l, hhi, hlo);
    }
    // 4) GEMM2: [G,F] @ [D,F]^T -> [G,D]
    {
        dim3 grid(DD / 128, GG / 128, NE);
        mma_gemm<<<grid, 256, GEMM_SMEM>>>(hhi, hlo, w3h, w3l, out, GG, DD, FF,
                                           (long long)GG * FF, (long long)DD * FF, (long long)GG * DD);
    }
}

// round 6
// speedup vs baseline: 4.4159x; 1.4399x over previous
#include <cuda_runtime.h>
#include <cuda_fp16.h>
#include <cstdint>

#define NE 8
#define DD 1024
#define FF 4096
#define GG 2048

// ------------------------------ scratch (allocation-guard-safe) -------------
static __device__ __half g_xhi[(size_t)NE * GG * DD];
static __device__ __half g_xlo[(size_t)NE * GG * DD];
static __device__ __half g_w1h[(size_t)NE * FF * DD];  // w_in^T  [e][F][D] fp16
static __device__ __half g_w2h[(size_t)NE * FF * DD];  // w_swiglu^T
static __device__ __half g_w3h[(size_t)NE * DD * FF];  // w_out^T [e][D][F]
static __device__ __half g_hhi[(size_t)NE * GG * FF];
static __device__ __half g_hlo[(size_t)NE * GG * FF];

// ------------------------------ helpers -------------------------------------
__device__ __forceinline__ uint32_t smem_u32(const void* p) {
    uint32_t a;
    asm("{ .reg .u64 t; cvta.to.shared.u64 t, %1; cvt.u32.u64 %0, t; }" : "=r"(a) : "l"(p));
    return a;
}

// Tile row = 32 fp16 (64B), 16B chunks c=0..3, XOR swizzle c' = c ^ ((row>>1)&3):
// conflict-free for both cp.async stores and ldmatrix 8-row phases.
__device__ __forceinline__ uint32_t tileoff(int row, int c) {
    return (uint32_t)((row << 6) + (((c ^ ((row >> 1) & 3))) << 4));
}

#define CP_ASYNC(dst, src) \
    asm volatile("cp.async.cg.shared.global [%0], [%1], 16;" :: "r"(dst), "l"(src) : "memory")
#define CP_COMMIT() asm volatile("cp.async.commit_group;" ::: "memory")
#define CP_WAIT0()  asm volatile("cp.async.wait_group 0;" ::: "memory")
#define CP_WAIT1()  asm volatile("cp.async.wait_group 1;" ::: "memory")
#define CP_WAIT2()  asm volatile("cp.async.wait_group 2;" ::: "memory")

#define LDSM4(r, addr) \
    asm volatile("ldmatrix.sync.aligned.m8n8.x4.shared.b16 {%0,%1,%2,%3}, [%4];" \
                 : "=r"((r)[0]), "=r"((r)[1]), "=r"((r)[2]), "=r"((r)[3]) : "r"(addr))

#define MMA(c, a, b) \
    asm volatile("mma.sync.aligned.m16n8k16.row.col.f32.f16.f16.f32 " \
                 "{%0,%1,%2,%3}, {%4,%5,%6,%7}, {%8,%9}, {%0,%1,%2,%3};" \
                 : "+f"((c)[0]), "+f"((c)[1]), "+f"((c)[2]), "+f"((c)[3]) \
                 : "r"((a)[0]), "r"((a)[1]), "r"((a)[2]), "r"((a)[3]), \
                   "r"((b)[0]), "r"((b)[1]))

// ============================================================================
// Fused GEMM1-pair + SwiGLU:
//   mid = x @ w1^T ; gate = x @ w2^T ; h = silu(mid)*gate -> hhi/hlo fp16
// x split into fp16 hi/lo (2-product exact-A); weights single fp16.
// CTA tile m128 x n64, k-chunk 32, 3-stage cp.async pipeline.
// 8 warps 2(m)x4(n); warp tile m64 x n16 per output.
// ============================================================================
#define FSTG 24576   // Ahi(8K) Alo(8K) B1(4K) B2(4K)
#define FUSED_SMEM (3 * FSTG)

__global__ __launch_bounds__(256)
void fused_gemm1_swiglu(const __half* __restrict__ Ahi_g, const __half* __restrict__ Alo_g,
                        const __half* __restrict__ B1_g, const __half* __restrict__ B2_g,
                        __half* __restrict__ Hhi_g, __half* __restrict__ Hlo_g)
{
    extern __shared__ char smem[];
    const uint32_t sb = smem_u32(smem);
    const int tid = threadIdx.x, wid = tid >> 5, lane = tid & 31;
    const int wm = wid >> 2, wn = wid & 3;

    const long long e = blockIdx.z;
    const __half* Ahi = Ahi_g + e * (long long)GG * DD;
    const __half* Alo = Alo_g + e * (long long)GG * DD;
    const __half* B1  = B1_g  + e * (long long)FF * DD;
    const __half* B2  = B2_g  + e * (long long)FF * DD;
    __half* Hhi = Hhi_g + e * (long long)GG * FF;
    __half* Hlo = Hlo_g + e * (long long)GG * FF;

    const int rowA0 = blockIdx.y * 128;
    const int colB0 = blockIdx.x * 64;

    float acc1[4][2][4], acc2[4][2][4];
    #pragma unroll
    for (int i = 0; i < 4; i++)
        #pragma unroll
        for (int j = 0; j < 2; j++)
            #pragma unroll
            for (int k = 0; k < 4; k++) { acc1[i][j][k] = 0.f; acc2[i][j][k] = 0.f; }

    const int nC = DD >> 5;

    auto load_stage = [&](int c, int s) {
        const uint32_t base = sb + s * FSTG;
        const int kc = c << 5;
        #pragma unroll
        for (int i = 0; i < 2; i++) {
            const int idx = tid + (i << 8);
            const int row = idx >> 2, ch = idx & 3;
            const uint32_t o = tileoff(row, ch);
            const size_t g = (size_t)(rowA0 + row) * DD + kc + ch * 8;
            CP_ASYNC(base + o,        Ahi + g);
            CP_ASYNC(base + 8192 + o, Alo + g);
        }
        {
            const int row = tid >> 2, ch = tid & 3;
            const uint32_t o = tileoff(row, ch);
            const size_t g = (size_t)(colB0 + row) * DD + kc + ch * 8;
            CP_ASYNC(base + 16384 + o, B1 + g);
            CP_ASYNC(base + 20480 + o, B2 + g);
        }
        CP_COMMIT();
    };

    load_stage(0, 0);
    load_stage(1, 1);

    int s = 0;
    for (int c = 0; c < nC; c++) {
        if (c + 2 < nC) {
            int s2 = s + 2; if (s2 >= 3) s2 -= 3;
            load_stage(c + 2, s2);
            CP_WAIT2();
        } else if (c + 1 < nC) CP_WAIT1();
        else                   CP_WAIT0();
        __syncthreads();

        const uint32_t tb = sb + s * FSTG;

        #pragma unroll
        for (int ks = 0; ks < 2; ks++) {
            const int ch = ks * 2 + (lane >> 4);
            uint32_t ah[4][4], al[4][4], b1[2][2], b2[2][2];
            #pragma unroll
            for (int mb = 0; mb < 4; mb++) {
                const int row = wm * 64 + mb * 16 + (lane & 15);
                const uint32_t o = tileoff(row, ch);
                LDSM4(ah[mb], tb + o);
                LDSM4(al[mb], tb + 8192 + o);
            }
            {
                const int row = wn * 16 + (lane & 15);
                const uint32_t o = tileoff(row, ch);
                uint32_t r[4];
                LDSM4(r, tb + 16384 + o);
                b1[0][0] = r[0]; b1[0][1] = r[2]; b1[1][0] = r[1]; b1[1][1] = r[3];
                LDSM4(r, tb + 20480 + o);
                b2[0][0] = r[0]; b2[0][1] = r[2]; b2[1][0] = r[1]; b2[1][1] = r[3];
            }
            #pragma unroll
            for (int mb = 0; mb < 4; mb++)
                #pragma unroll
                for (int nb = 0; nb < 2; nb++) {
                    MMA(acc1[mb][nb], ah[mb], b1[nb]);
                    MMA(acc1[mb][nb], al[mb], b1[nb]);
                    MMA(acc2[mb][nb], ah[mb], b2[nb]);
                    MMA(acc2[mb][nb], al[mb], b2[nb]);
                }
        }
        __syncthreads();
        if (++s == 3) s = 0;
    }

    // epilogue: h = silu(mid)*gate, split to fp16 hi/lo, store
    #pragma unroll
    for (int mb = 0; mb < 4; mb++) {
        const int m0 = rowA0 + wm * 64 + mb * 16 + (lane >> 2);
        #pragma unroll
        for (int nb = 0; nb < 2; nb++) {
            const int n = colB0 + wn * 16 + nb * 8 + (lane & 3) * 2;
            #pragma unroll
            for (int half_i = 0; half_i < 2; half_i++) {
                const int m = m0 + half_i * 8;
                float md0 = acc1[mb][nb][half_i * 2 + 0], gt0 = acc2[mb][nb][half_i * 2 + 0];
                float md1 = acc1[mb][nb][half_i * 2 + 1], gt1 = acc2[mb][nb][half_i * 2 + 1];
                float h0 = md0 / (1.f + __expf(-md0)) * gt0;
                float h1 = md1 / (1.f + __expf(-md1)) * gt1;
                __half h0h = __float2half(h0);
                __half h1h = __float2half(h1);
                __half h0l = __float2half(h0 - __half2float(h0h));
                __half h1l = __float2half(h1 - __half2float(h1h));
                *reinterpret_cast<ushort2*>(&Hhi[(size_t)m * FF + n]) =
                    make_ushort2(__half_as_ushort(h0h), __half_as_ushort(h1h));
                *reinterpret_cast<ushort2*>(&Hlo[(size_t)m * FF + n]) =
                    make_ushort2(__half_as_ushort(h0l), __half_as_ushort(h1l));
            }
        }
    }
}

// ============================================================================
// GEMM2: C = (Ahi + Alo) @ B^T ; A:[M,K] fp16 hi/lo, B:[N,K] fp16 single.
// 128x128x32 CTA tile, 3-stage cp.async pipeline, 8 warps 2(m)x4(n), warp m64xn32.
// ============================================================================
#define GSTG 24576   // Ahi(8K) Alo(8K) B(8K)
#define GEMM_SMEM (3 * GSTG)

__global__ __launch_bounds__(256)
void mma_gemm(const __half* __restrict__ Ahi_g, const __half* __restrict__ Alo_g,
              const __half* __restrict__ B_g, float* __restrict__ Cg,
              int M, int N, int K,
              long long strA, long long strB, long long strC)
{
    extern __shared__ char smem[];
    const uint32_t sb = smem_u32(smem);
    const int tid = threadIdx.x, wid = tid >> 5, lane = tid & 31;
    const int wm = wid >> 2, wn = wid & 3;

    const __half* Ahi = Ahi_g + (long long)blockIdx.z * strA;
    const __half* Alo = Alo_g + (long long)blockIdx.z * strA;
    const __half* B   = B_g   + (long long)blockIdx.z * strB;
    float* C = Cg + (long long)blockIdx.z * strC;

    const int rowA0 = blockIdx.y * 128;
    const int colB0 = blockIdx.x * 128;

    float acc[4][4][4];
    #pragma unroll
    for (int i = 0; i < 4; i++)
        #pragma unroll
        for (int j = 0; j < 4; j++)
            #pragma unroll
            for (int k = 0; k < 4; k++) acc[i][j][k] = 0.f;

    const int nC = K >> 5;

    auto load_stage = [&](int c, int s) {
        const uint32_t base = sb + s * GSTG;
        const int kc = c << 5;
        #pragma unroll
        for (int i = 0; i < 2; i++) {
            const int idx = tid + (i << 8);
            const int row = idx >> 2, ch = idx & 3;
            const uint32_t o = tileoff(row, ch);
            const size_t ga = (size_t)(rowA0 + row) * K + kc + ch * 8;
            const size_t gb = (size_t)(colB0 + row) * K + kc + ch * 8;
            CP_ASYNC(base + o,         Ahi + ga);
            CP_ASYNC(base + 8192 + o,  Alo + ga);
            CP_ASYNC(base + 16384 + o, B + gb);
        }
        CP_COMMIT();
    };

    load_stage(0, 0);
    load_stage(1, 1);

    int s = 0;
    for (int c = 0; c < nC; c++) {
        if (c + 2 < nC) {
            int s2 = s + 2; if (s2 >= 3) s2 -= 3;
            load_stage(c + 2, s2);
            CP_WAIT2();
        } else if (c + 1 < nC) CP_WAIT1();
        else                   CP_WAIT0();
        __syncthreads();

        const uint32_t tb = sb + s * GSTG;

        #pragma unroll
        for (int ks = 0; ks < 2; ks++) {
            uint32_t ah[4][4], al[4][4], bh[4][2];
            const int ch = ks * 2 + (lane >> 4);
            #pragma unroll
            for (int mb = 0; mb < 4; mb++) {
                const int row = wm * 64 + mb * 16 + (lane & 15);
                const uint32_t o = tileoff(row, ch);
                LDSM4(ah[mb], tb + o);
                LDSM4(al[mb], tb + 8192 + o);
            }
            #pragma unroll
            for (int nb16 = 0; nb16 < 2; nb16++) {
                const int row = wn * 32 + nb16 * 16 + (lane & 15);
                const uint32_t o = tileoff(row, ch);
                uint32_t r[4];
                LDSM4(r, tb + 16384 + o);
                bh[nb16 * 2][0] = r[0]; bh[nb16 * 2][1] = r[2];
                bh[nb16 * 2 + 1][0] = r[1]; bh[nb16 * 2 + 1][1] = r[3];
            }
            #pragma unroll
            for (int mb = 0; mb < 4; mb++)
                #pragma unroll
                for (int nb = 0; nb < 4; nb++) {
                    MMA(acc[mb][nb], ah[mb], bh[nb]);
                    MMA(acc[mb][nb], al[mb], bh[nb]);
                }
        }
        __syncthreads();
        if (++s == 3) s = 0;
    }

    #pragma unroll
    for (int mb = 0; mb < 4; mb++) {
        const int m = rowA0 + wm * 64 + mb * 16 + (lane >> 2);
        #pragma unroll
        for (int nb = 0; nb < 4; nb++) {
            const int n = colB0 + wn * 32 + nb * 8 + (lane & 3) * 2;
            *reinterpret_cast<float2*>(&C[(size_t)m * N + n]) =
                make_float2(acc[mb][nb][0], acc[mb][nb][1]);
            *reinterpret_cast<float2*>(&C[(size_t)(m + 8) * N + n]) =
                make_float2(acc[mb][nb][2], acc[mb][nb][3]);
        }
    }
}

// ------------------------------ conversion kernels --------------------------
__global__ __launch_bounds__(256)
void split_f32_kernel(const float* __restrict__ in, __half* __restrict__ hi,
                      __half* __restrict__ lo, size_t n4)
{
    size_t i = (size_t)blockIdx.x * blockDim.x + threadIdx.x;
    if (i >= n4) return;
    float4 v = reinterpret_cast<const float4*>(in)[i];
    __half h0 = __float2half(v.x), h1 = __float2half(v.y);
    __half h2 = __float2half(v.z), h3 = __float2half(v.w);
    __half l0 = __float2half(v.x - __half2float(h0));
    __half l1 = __float2half(v.y - __half2float(h1));
    __half l2 = __float2half(v.z - __half2float(h2));
    __half l3 = __float2half(v.w - __half2float(h3));
    reinterpret_cast<ushort4*>(hi)[i] = make_ushort4(__half_as_ushort(h0), __half_as_ushort(h1),
                                                     __half_as_ushort(h2), __half_as_ushort(h3));
    reinterpret_cast<ushort4*>(lo)[i] = make_ushort4(__half_as_ushort(l0), __half_as_ushort(l1),
                                                     __half_as_ushort(l2), __half_as_ushort(l3));
}

// w [e][K][N] fp32 -> wT [e][N][K] fp16 (32x32 tiles)
__global__ __launch_bounds__(256)
void transpose_h_kernel(const float* __restrict__ w, __half* __restrict__ wT, int K, int N)
{
    __shared__ float t[32][33];
    const int e = blockIdx.z;
    const int n0 = blockIdx.x * 32, k0 = blockIdx.y * 32;
    const int tx = threadIdx.x, ty = threadIdx.y;   // (32, 8)
    const float* we = w + (size_t)e * K * N;
    #pragma unroll
    for (int j = 0; j < 4; j++)
        t[ty + 8 * j][tx] = we[(size_t)(k0 + ty + 8 * j) * N + n0 + tx];
    __syncthreads();
    __half* wo = wT + (size_t)e * N * K;
    #pragma unroll
    for (int j = 0; j < 4; j++)
        wo[(size_t)(n0 + ty + 8 * j) * K + k0 + tx] = __float2half(t[tx][ty + 8 * j]);
}

// ------------------------------ launch --------------------------------------
extern "C" void kernel_launch(void* const* d_in, const int* in_sizes, int n_in,
                              void* d_out, int out_size)
{
    const float* x    = (const float*)d_in[0];
    const float* win  = (const float*)d_in[1];
    const float* wsw  = (const float*)d_in[2];
    const float* wout = (const float*)d_in[3];
    float* out = (float*)d_out;

    __half *xhi, *xlo, *w1h, *w2h, *w3h, *hhi, *hlo;
    cudaGetSymbolAddress((void**)&xhi, g_xhi);  cudaGetSymbolAddress((void**)&xlo, g_xlo);
    cudaGetSymbolAddress((void**)&w1h, g_w1h);  cudaGetSymbolAddress((void**)&w2h, g_w2h);
    cudaGetSymbolAddress((void**)&w3h, g_w3h);
    cudaGetSymbolAddress((void**)&hhi, g_hhi);  cudaGetSymbolAddress((void**)&hlo, g_hlo);

    cudaFuncSetAttribute(fused_gemm1_swiglu, cudaFuncAttributeMaxDynamicSharedMemorySize, FUSED_SMEM);
    cudaFuncSetAttribute(mma_gemm, cudaFuncAttributeMaxDynamicSharedMemorySize, GEMM_SMEM);

    // 1) split x into fp16 hi/lo
    {
        size_t n4 = (size_t)NE * GG * DD / 4;
        split_f32_kernel<<<(unsigned)((n4 + 255) / 256), 256>>>(x, xhi, xlo, n4);
    }
    // 2) transpose weights to [N,K] fp16
    {
        dim3 blk(32, 8);
        transpose_h_kernel<<<dim3(FF / 32, DD / 32, NE), blk>>>(win,  w1h, DD, FF);
        transpose_h_kernel<<<dim3(FF / 32, DD / 32, NE), blk>>>(wsw,  w2h, DD, FF);
        transpose_h_kernel<<<dim3(DD / 32, FF / 32, NE), blk>>>(wout, w3h, FF, DD);
    }
    // 3) fused GEMM1 pair + SwiGLU -> hidden hi/lo fp16
    {
        dim3 grid(FF / 64, GG / 128, NE);
        fused_gemm1_swiglu<<<grid, 256, FUSED_SMEM>>>(xhi, xlo, w1h, w2h, hhi, hlo);
    }
    // 4) GEMM2: [G,F] @ [D,F]^T -> [G,D]
    {
        dim3 grid(DD / 128, GG / 128, NE);
        mma_gemm<<<grid, 256, GEMM_SMEM>>>(hhi, hlo, w3h, out, GG, DD, FF,
                                           (long long)GG * FF, (long long)DD * FF, (long long)GG * DD);
    }
}

// round 8
// speedup vs baseline: 5.3297x; 1.2069x over previous
#include <cuda_runtime.h>
#include <cuda_fp16.h>
#include <cstdint>

#define NE 8
#define DD 1024
#define FF 4096
#define GG 2048

// ------------------------------ scratch (allocation-guard-safe) -------------
static __device__ __half g_xhi[(size_t)NE * GG * DD];
static __device__ __half g_xlo[(size_t)NE * GG * DD];
static __device__ __half g_w1h[(size_t)NE * FF * DD];  // w_in^T  [e][F][D] fp16
static __device__ __half g_w2h[(size_t)NE * FF * DD];  // w_swiglu^T
static __device__ __half g_w3h[(size_t)NE * DD * FF];  // w_out^T [e][D][F]
static __device__ __half g_h  [(size_t)NE * GG * FF];  // hidden, single fp16

// ------------------------------ helpers -------------------------------------
__device__ __forceinline__ uint32_t smem_u32(const void* p) {
    uint32_t a;
    asm("{ .reg .u64 t; cvta.to.shared.u64 t, %1; cvt.u32.u64 %0, t; }" : "=r"(a) : "l"(p));
    return a;
}

// Tile row = 32 fp16 (64B), 16B chunks c=0..3, XOR swizzle c' = c ^ ((row>>1)&3):
// conflict-free for both cp.async stores and ldmatrix 8-row phases.
__device__ __forceinline__ uint32_t tileoff(int row, int c) {
    return (uint32_t)((row << 6) + (((c ^ ((row >> 1) & 3))) << 4));
}

#define CP_ASYNC(dst, src) \
    asm volatile("cp.async.cg.shared.global [%0], [%1], 16;" :: "r"(dst), "l"(src) : "memory")
#define CP_COMMIT() asm volatile("cp.async.commit_group;" ::: "memory")
#define CP_WAIT0()  asm volatile("cp.async.wait_group 0;" ::: "memory")
#define CP_WAIT1()  asm volatile("cp.async.wait_group 1;" ::: "memory")
#define CP_WAIT2()  asm volatile("cp.async.wait_group 2;" ::: "memory")

#define LDSM4(r, addr) \
    asm volatile("ldmatrix.sync.aligned.m8n8.x4.shared.b16 {%0,%1,%2,%3}, [%4];" \
                 : "=r"((r)[0]), "=r"((r)[1]), "=r"((r)[2]), "=r"((r)[3]) : "r"(addr))

#define MMA(c, a, b) \
    asm volatile("mma.sync.aligned.m16n8k16.row.col.f32.f16.f16.f32 " \
                 "{%0,%1,%2,%3}, {%4,%5,%6,%7}, {%8,%9}, {%0,%1,%2,%3};" \
                 : "+f"((c)[0]), "+f"((c)[1]), "+f"((c)[2]), "+f"((c)[3]) \
                 : "r"((a)[0]), "r"((a)[1]), "r"((a)[2]), "r"((a)[3]), \
                   "r"((b)[0]), "r"((b)[1]))

// ============================================================================
// Fused GEMM1-pair + SwiGLU:
//   mid = x @ w1^T ; gate = x @ w2^T ; h = silu(mid)*gate -> fp16
// x split into fp16 hi/lo (2-product exact-A); weights single fp16.
// CTA tile m128 x n64, k-chunk 32, 3-stage cp.async pipeline.
// 8 warps 4(m)x2(n); warp tile m32 x n32 per output (better LDSM:MMA ratio).
// ============================================================================
#define FSTG 24576   // Ahi(8K) Alo(8K) B1(4K) B2(4K)
#define FUSED_SMEM (3 * FSTG)

__global__ __launch_bounds__(256)
void fused_gemm1_swiglu(const __half* __restrict__ Ahi_g, const __half* __restrict__ Alo_g,
                        const __half* __restrict__ B1_g, const __half* __restrict__ B2_g,
                        __half* __restrict__ H_g)
{
    extern __shared__ char smem[];
    const uint32_t sb = smem_u32(smem);
    const int tid = threadIdx.x, wid = tid >> 5, lane = tid & 31;
    const int wm = wid >> 1, wn = wid & 1;   // 4 x 2 warp grid

    const long long e = blockIdx.z;
    const __half* Ahi = Ahi_g + e * (long long)GG * DD;
    const __half* Alo = Alo_g + e * (long long)GG * DD;
    const __half* B1  = B1_g  + e * (long long)FF * DD;
    const __half* B2  = B2_g  + e * (long long)FF * DD;
    __half* H = H_g + e * (long long)GG * FF;

    const int rowA0 = blockIdx.y * 128;
    const int colB0 = blockIdx.x * 64;

    float acc1[2][4][4], acc2[2][4][4];
    #pragma unroll
    for (int i = 0; i < 2; i++)
        #pragma unroll
        for (int j = 0; j < 4; j++)
            #pragma unroll
            for (int k = 0; k < 4; k++) { acc1[i][j][k] = 0.f; acc2[i][j][k] = 0.f; }

    const int nC = DD >> 5;

    auto load_stage = [&](int c, int s) {
        const uint32_t base = sb + s * FSTG;
        const int kc = c << 5;
        #pragma unroll
        for (int i = 0; i < 2; i++) {
            const int idx = tid + (i << 8);
            const int row = idx >> 2, ch = idx & 3;
            const uint32_t o = tileoff(row, ch);
            const size_t g = (size_t)(rowA0 + row) * DD + kc + ch * 8;
            CP_ASYNC(base + o,        Ahi + g);
            CP_ASYNC(base + 8192 + o, Alo + g);
        }
        {
            const int row = tid >> 2, ch = tid & 3;
            const uint32_t o = tileoff(row, ch);
            const size_t g = (size_t)(colB0 + row) * DD + kc + ch * 8;
            CP_ASYNC(base + 16384 + o, B1 + g);
            CP_ASYNC(base + 20480 + o, B2 + g);
        }
        CP_COMMIT();
    };

    load_stage(0, 0);
    load_stage(1, 1);

    int s = 0;
    for (int c = 0; c < nC; c++) {
        if (c + 2 < nC) {
            int s2 = s + 2; if (s2 >= 3) s2 -= 3;
            load_stage(c + 2, s2);
            CP_WAIT2();
        } else if (c + 1 < nC) CP_WAIT1();
        else                   CP_WAIT0();
        __syncthreads();

        const uint32_t tb = sb + s * FSTG;

        #pragma unroll
        for (int ks = 0; ks < 2; ks++) {
            const int ch = ks * 2 + (lane >> 4);
            uint32_t ah[2][4], al[2][4], b1[4][2], b2[4][2];
            #pragma unroll
            for (int mb = 0; mb < 2; mb++) {
                const int row = wm * 32 + mb * 16 + (lane & 15);
                const uint32_t o = tileoff(row, ch);
                LDSM4(ah[mb], tb + o);
                LDSM4(al[mb], tb + 8192 + o);
            }
            #pragma unroll
            for (int nb16 = 0; nb16 < 2; nb16++) {
                const int row = wn * 32 + nb16 * 16 + (lane & 15);
                const uint32_t o = tileoff(row, ch);
                uint32_t r[4];
                LDSM4(r, tb + 16384 + o);
                b1[nb16 * 2][0] = r[0]; b1[nb16 * 2][1] = r[2];
                b1[nb16 * 2 + 1][0] = r[1]; b1[nb16 * 2 + 1][1] = r[3];
                LDSM4(r, tb + 20480 + o);
                b2[nb16 * 2][0] = r[0]; b2[nb16 * 2][1] = r[2];
                b2[nb16 * 2 + 1][0] = r[1]; b2[nb16 * 2 + 1][1] = r[3];
            }
            #pragma unroll
            for (int mb = 0; mb < 2; mb++)
                #pragma unroll
                for (int nb = 0; nb < 4; nb++) {
                    MMA(acc1[mb][nb], ah[mb], b1[nb]);
                    MMA(acc1[mb][nb], al[mb], b1[nb]);
                    MMA(acc2[mb][nb], ah[mb], b2[nb]);
                    MMA(acc2[mb][nb], al[mb], b2[nb]);
                }
        }
        __syncthreads();
        if (++s == 3) s = 0;
    }

    // epilogue: h = silu(mid)*gate -> single fp16
    #pragma unroll
    for (int mb = 0; mb < 2; mb++) {
        const int m0 = rowA0 + wm * 32 + mb * 16 + (lane >> 2);
        #pragma unroll
        for (int nb = 0; nb < 4; nb++) {
            const int n = colB0 + wn * 32 + nb * 8 + (lane & 3) * 2;
            #pragma unroll
            for (int half_i = 0; half_i < 2; half_i++) {
                const int m = m0 + half_i * 8;
                float md0 = acc1[mb][nb][half_i * 2 + 0], gt0 = acc2[mb][nb][half_i * 2 + 0];
                float md1 = acc1[mb][nb][half_i * 2 + 1], gt1 = acc2[mb][nb][half_i * 2 + 1];
                float h0 = md0 / (1.f + __expf(-md0)) * gt0;
                float h1 = md1 / (1.f + __expf(-md1)) * gt1;
                *reinterpret_cast<ushort2*>(&H[(size_t)m * FF + n]) =
                    make_ushort2(__half_as_ushort(__float2half(h0)),
                                 __half_as_ushort(__float2half(h1)));
            }
        }
    }
}

// ============================================================================
// GEMM2: C = A @ B^T ; A:[M,K] fp16 single, B:[N,K] fp16 single (1-product).
// 128x128x32 CTA tile, 3-stage cp.async pipeline, 8 warps 2(m)x4(n), warp m64xn32.
// ============================================================================
#define GSTG 16384   // A(8K) B(8K)
#define GEMM_SMEM (3 * GSTG)

__global__ __launch_bounds__(256)
void mma_gemm(const __half* __restrict__ A_g, const __half* __restrict__ B_g,
              float* __restrict__ Cg, int M, int N, int K,
              long long strA, long long strB, long long strC)
{
    extern __shared__ char smem[];
    const uint32_t sb = smem_u32(smem);
    const int tid = threadIdx.x, wid = tid >> 5, lane = tid & 31;
    const int wm = wid >> 2, wn = wid & 3;

    const __half* A = A_g + (long long)blockIdx.z * strA;
    const __half* B = B_g + (long long)blockIdx.z * strB;
    float* C = Cg + (long long)blockIdx.z * strC;

    const int rowA0 = blockIdx.y * 128;
    const int colB0 = blockIdx.x * 128;

    float acc[4][4][4];
    #pragma unroll
    for (int i = 0; i < 4; i++)
        #pragma unroll
        for (int j = 0; j < 4; j++)
            #pragma unroll
            for (int k = 0; k < 4; k++) acc[i][j][k] = 0.f;

    const int nC = K >> 5;

    auto load_stage = [&](int c, int s) {
        const uint32_t base = sb + s * GSTG;
        const int kc = c << 5;
        #pragma unroll
        for (int i = 0; i < 2; i++) {
            const int idx = tid + (i << 8);
            const int row = idx >> 2, ch = idx & 3;
            const uint32_t o = tileoff(row, ch);
            CP_ASYNC(base + o,        A + (size_t)(rowA0 + row) * K + kc + ch * 8);
            CP_ASYNC(base + 8192 + o, B + (size_t)(colB0 + row) * K + kc + ch * 8);
        }
        CP_COMMIT();
    };

    load_stage(0, 0);
    load_stage(1, 1);

    int s = 0;
    for (int c = 0; c < nC; c++) {
        if (c + 2 < nC) {
            int s2 = s + 2; if (s2 >= 3) s2 -= 3;
            load_stage(c + 2, s2);
            CP_WAIT2();
        } else if (c + 1 < nC) CP_WAIT1();
        else                   CP_WAIT0();
        __syncthreads();

        const uint32_t tb = sb + s * GSTG;

        #pragma unroll
        for (int ks = 0; ks < 2; ks++) {
            uint32_t ah[4][4], bh[4][2];
            const int ch = ks * 2 + (lane >> 4);
            #pragma unroll
            for (int mb = 0; mb < 4; mb++) {
                const int row = wm * 64 + mb * 16 + (lane & 15);
                LDSM4(ah[mb], tb + tileoff(row, ch));
            }
            #pragma unroll
            for (int nb16 = 0; nb16 < 2; nb16++) {
                const int row = wn * 32 + nb16 * 16 + (lane & 15);
                uint32_t r[4];
                LDSM4(r, tb + 8192 + tileoff(row, ch));
                bh[nb16 * 2][0] = r[0]; bh[nb16 * 2][1] = r[2];
                bh[nb16 * 2 + 1][0] = r[1]; bh[nb16 * 2 + 1][1] = r[3];
            }
            #pragma unroll
            for (int mb = 0; mb < 4; mb++)
                #pragma unroll
                for (int nb = 0; nb < 4; nb++)
                    MMA(acc[mb][nb], ah[mb], bh[nb]);
        }
        __syncthreads();
        if (++s == 3) s = 0;
    }

    #pragma unroll
    for (int mb = 0; mb < 4; mb++) {
        const int m = rowA0 + wm * 64 + mb * 16 + (lane >> 2);
        #pragma unroll
        for (int nb = 0; nb < 4; nb++) {
            const int n = colB0 + wn * 32 + nb * 8 + (lane & 3) * 2;
            *reinterpret_cast<float2*>(&C[(size_t)m * N + n]) =
                make_float2(acc[mb][nb][0], acc[mb][nb][1]);
            *reinterpret_cast<float2*>(&C[(size_t)(m + 8) * N + n]) =
                make_float2(acc[mb][nb][2], acc[mb][nb][3]);
        }
    }
}

// ------------------------------ conversion kernels --------------------------
__global__ __launch_bounds__(256)
void split_f32_kernel(const float* __restrict__ in, __half* __restrict__ hi,
                      __half* __restrict__ lo, size_t n4)
{
    size_t i = (size_t)blockIdx.x * blockDim.x + threadIdx.x;
    if (i >= n4) return;
    float4 v = reinterpret_cast<const float4*>(in)[i];
    __half h0 = __float2half(v.x), h1 = __float2half(v.y);
    __half h2 = __float2half(v.z), h3 = __float2half(v.w);
    __half l0 = __float2half(v.x - __half2float(h0));
    __half l1 = __float2half(v.y - __half2float(h1));
    __half l2 = __float2half(v.z - __half2float(h2));
    __half l3 = __float2half(v.w - __half2float(h3));
    reinterpret_cast<ushort4*>(hi)[i] = make_ushort4(__half_as_ushort(h0), __half_as_ushort(h1),
                                                     __half_as_ushort(h2), __half_as_ushort(h3));
    reinterpret_cast<ushort4*>(lo)[i] = make_ushort4(__half_as_ushort(l0), __half_as_ushort(l1),
                                                     __half_as_ushort(l2), __half_as_ushort(l3));
}

// w [e][K][N] fp32 -> wT [e][N][K] fp16 (32x32 tiles)
__global__ __launch_bounds__(256)
void transpose_h_kernel(const float* __restrict__ w, __half* __restrict__ wT, int K, int N)
{
    __shared__ float t[32][33];
    const int e = blockIdx.z;
    const int n0 = blockIdx.x * 32, k0 = blockIdx.y * 32;
    const int tx = threadIdx.x, ty = threadIdx.y;   // (32, 8)
    const float* we = w + (size_t)e * K * N;
    #pragma unroll
    for (int j = 0; j < 4; j++)
        t[ty + 8 * j][tx] = we[(size_t)(k0 + ty + 8 * j) * N + n0 + tx];
    __syncthreads();
    __half* wo = wT + (size_t)e * N * K;
    #pragma unroll
    for (int j = 0; j < 4; j++)
        wo[(size_t)(n0 + ty + 8 * j) * K + k0 + tx] = __float2half(t[tx][ty + 8 * j]);
}

// ------------------------------ launch --------------------------------------
extern "C" void kernel_launch(void* const* d_in, const int* in_sizes, int n_in,
                              void* d_out, int out_size)
{
    const float* x    = (const float*)d_in[0];
    const float* win  = (const float*)d_in[1];
    const float* wsw  = (const float*)d_in[2];
    const float* wout = (const float*)d_in[3];
    float* out = (float*)d_out;

    __half *xhi, *xlo, *w1h, *w2h, *w3h, *h;
    cudaGetSymbolAddress((void**)&xhi, g_xhi);  cudaGetSymbolAddress((void**)&xlo, g_xlo);
    cudaGetSymbolAddress((void**)&w1h, g_w1h);  cudaGetSymbolAddress((void**)&w2h, g_w2h);
    cudaGetSymbolAddress((void**)&w3h, g_w3h);
    cudaGetSymbolAddress((void**)&h, g_h);

    cudaFuncSetAttribute(fused_gemm1_swiglu, cudaFuncAttributeMaxDynamicSharedMemorySize, FUSED_SMEM);
    cudaFuncSetAttribute(mma_gemm, cudaFuncAttributeMaxDynamicSharedMemorySize, GEMM_SMEM);

    // 1) split x into fp16 hi/lo
    {
        size_t n4 = (size_t)NE * GG * DD / 4;
        split_f32_kernel<<<(unsigned)((n4 + 255) / 256), 256>>>(x, xhi, xlo, n4);
    }
    // 2) transpose weights to [N,K] fp16
    {
        dim3 blk(32, 8);
        transpose_h_kernel<<<dim3(FF / 32, DD / 32, NE), blk>>>(win,  w1h, DD, FF);
        transpose_h_kernel<<<dim3(FF / 32, DD / 32, NE), blk>>>(wsw,  w2h, DD, FF);
        transpose_h_kernel<<<dim3(DD / 32, FF / 32, NE), blk>>>(wout, w3h, FF, DD);
    }
    // 3) fused GEMM1 pair + SwiGLU -> hidden fp16
    {
        dim3 grid(FF / 64, GG / 128, NE);
        fused_gemm1_swiglu<<<grid, 256, FUSED_SMEM>>>(xhi, xlo, w1h, w2h, h);
    }
    // 4) GEMM2: [G,F] @ [D,F]^T -> [G,D]
    {
        dim3 grid(DD / 128, GG / 128, NE);
        mma_gemm<<<grid, 256, GEMM_SMEM>>>(h, w3h, out, GG, DD, FF,
                                           (long long)GG * FF, (long long)FF * DD, (long long)GG * DD);
    }
}

// round 10
// speedup vs baseline: 7.5367x; 1.4141x over previous
#include <cuda_runtime.h>
#include <cuda_fp16.h>
#include <cstdint>

#define NE 8
#define DD 1024
#define FF 4096
#define GG 2048

// ------------------------------ scratch (allocation-guard-safe) -------------
static __device__ __half g_xh [(size_t)NE * GG * DD];  // x fp16
static __device__ __half g_w1h[(size_t)NE * FF * DD];  // w_in^T  [e][F][D] fp16
static __device__ __half g_w2h[(size_t)NE * FF * DD];  // w_swiglu^T
static __device__ __half g_w3h[(size_t)NE * DD * FF];  // w_out^T [e][D][F]
static __device__ __half g_h  [(size_t)NE * GG * FF];  // hidden fp16

// ------------------------------ helpers -------------------------------------
__device__ __forceinline__ uint32_t smem_u32(const void* p) {
    uint32_t a;
    asm("{ .reg .u64 t; cvta.to.shared.u64 t, %1; cvt.u32.u64 %0, t; }" : "=r"(a) : "l"(p));
    return a;
}

// Tile row = 32 fp16 (64B), 16B chunks c=0..3, XOR swizzle c' = c ^ ((row>>1)&3):
// conflict-free for both cp.async stores and ldmatrix 8-row phases.
__device__ __forceinline__ uint32_t tileoff(int row, int c) {
    return (uint32_t)((row << 6) + (((c ^ ((row >> 1) & 3))) << 4));
}

#define CP_ASYNC(dst, src) \
    asm volatile("cp.async.cg.shared.global [%0], [%1], 16;" :: "r"(dst), "l"(src) : "memory")
#define CP_COMMIT() asm volatile("cp.async.commit_group;" ::: "memory")
#define CP_WAIT0()  asm volatile("cp.async.wait_group 0;" ::: "memory")
#define CP_WAIT1()  asm volatile("cp.async.wait_group 1;" ::: "memory")
#define CP_WAIT2()  asm volatile("cp.async.wait_group 2;" ::: "memory")

#define LDSM4(r, addr) \
    asm volatile("ldmatrix.sync.aligned.m8n8.x4.shared.b16 {%0,%1,%2,%3}, [%4];" \
                 : "=r"((r)[0]), "=r"((r)[1]), "=r"((r)[2]), "=r"((r)[3]) : "r"(addr))

#define MMA(c, a, b) \
    asm volatile("mma.sync.aligned.m16n8k16.row.col.f32.f16.f16.f32 " \
                 "{%0,%1,%2,%3}, {%4,%5,%6,%7}, {%8,%9}, {%0,%1,%2,%3};" \
                 : "+f"((c)[0]), "+f"((c)[1]), "+f"((c)[2]), "+f"((c)[3]) \
                 : "r"((a)[0]), "r"((a)[1]), "r"((a)[2]), "r"((a)[3]), \
                   "r"((b)[0]), "r"((b)[1]))

// ============================================================================
// Fused GEMM1-pair + SwiGLU (pure fp16 operands):
//   mid = x @ w1^T ; gate = x @ w2^T ; h = silu(mid)*gate -> fp16
// CTA tile m128 x n64, k-chunk 32, 3-stage cp.async pipeline.
// 8 warps 4(m)x2(n); warp tile m32 x n32 per output.
// ============================================================================
#define FSTG 16384   // A(8K) B1(4K) B2(4K)
#define FUSED_SMEM (3 * FSTG)

__global__ __launch_bounds__(256)
void fused_gemm1_swiglu(const __half* __restrict__ A_g,
                        const __half* __restrict__ B1_g, const __half* __restrict__ B2_g,
                        __half* __restrict__ H_g)
{
    extern __shared__ char smem[];
    const uint32_t sb = smem_u32(smem);
    const int tid = threadIdx.x, wid = tid >> 5, lane = tid & 31;
    const int wm = wid >> 1, wn = wid & 1;   // 4 x 2 warp grid

    const long long e = blockIdx.z;
    const __half* A  = A_g  + e * (long long)GG * DD;
    const __half* B1 = B1_g + e * (long long)FF * DD;
    const __half* B2 = B2_g + e * (long long)FF * DD;
    __half* H = H_g + e * (long long)GG * FF;

    const int rowA0 = blockIdx.y * 128;
    const int colB0 = blockIdx.x * 64;

    float acc1[2][4][4], acc2[2][4][4];
    #pragma unroll
    for (int i = 0; i < 2; i++)
        #pragma unroll
        for (int j = 0; j < 4; j++)
            #pragma unroll
            for (int k = 0; k < 4; k++) { acc1[i][j][k] = 0.f; acc2[i][j][k] = 0.f; }

    const int nC = DD >> 5;

    auto load_stage = [&](int c, int s) {
        const uint32_t base = sb + s * FSTG;
        const int kc = c << 5;
        #pragma unroll
        for (int i = 0; i < 2; i++) {
            const int idx = tid + (i << 8);
            const int row = idx >> 2, ch = idx & 3;
            CP_ASYNC(base + tileoff(row, ch), A + (size_t)(rowA0 + row) * DD + kc + ch * 8);
        }
        {
            const int row = tid >> 2, ch = tid & 3;
            const uint32_t o = tileoff(row, ch);
            const size_t g = (size_t)(colB0 + row) * DD + kc + ch * 8;
            CP_ASYNC(base + 8192 + o,  B1 + g);
            CP_ASYNC(base + 12288 + o, B2 + g);
        }
        CP_COMMIT();
    };

    load_stage(0, 0);
    load_stage(1, 1);

    int s = 0;
    for (int c = 0; c < nC; c++) {
        if (c + 2 < nC) {
            int s2 = s + 2; if (s2 >= 3) s2 -= 3;
            load_stage(c + 2, s2);
            CP_WAIT2();
        } else if (c + 1 < nC) CP_WAIT1();
        else                   CP_WAIT0();
        __syncthreads();

        const uint32_t tb = sb + s * FSTG;

        #pragma unroll
        for (int ks = 0; ks < 2; ks++) {
            const int ch = ks * 2 + (lane >> 4);
            uint32_t ah[2][4], b1[4][2], b2[4][2];
            #pragma unroll
            for (int mb = 0; mb < 2; mb++) {
                const int row = wm * 32 + mb * 16 + (lane & 15);
                LDSM4(ah[mb], tb + tileoff(row, ch));
            }
            #pragma unroll
            for (int nb16 = 0; nb16 < 2; nb16++) {
                const int row = wn * 32 + nb16 * 16 + (lane & 15);
                const uint32_t o = tileoff(row, ch);
                uint32_t r[4];
                LDSM4(r, tb + 8192 + o);
                b1[nb16 * 2][0] = r[0]; b1[nb16 * 2][1] = r[2];
                b1[nb16 * 2 + 1][0] = r[1]; b1[nb16 * 2 + 1][1] = r[3];
                LDSM4(r, tb + 12288 + o);
                b2[nb16 * 2][0] = r[0]; b2[nb16 * 2][1] = r[2];
                b2[nb16 * 2 + 1][0] = r[1]; b2[nb16 * 2 + 1][1] = r[3];
            }
            #pragma unroll
            for (int mb = 0; mb < 2; mb++)
                #pragma unroll
                for (int nb = 0; nb < 4; nb++) {
                    MMA(acc1[mb][nb], ah[mb], b1[nb]);
                    MMA(acc2[mb][nb], ah[mb], b2[nb]);
                }
        }
        __syncthreads();
        if (++s == 3) s = 0;
    }

    // epilogue: h = silu(mid)*gate -> fp16
    #pragma unroll
    for (int mb = 0; mb < 2; mb++) {
        const int m0 = rowA0 + wm * 32 + mb * 16 + (lane >> 2);
        #pragma unroll
        for (int nb = 0; nb < 4; nb++) {
            const int n = colB0 + wn * 32 + nb * 8 + (lane & 3) * 2;
            #pragma unroll
            for (int half_i = 0; half_i < 2; half_i++) {
                const int m = m0 + half_i * 8;
                float md0 = acc1[mb][nb][half_i * 2 + 0], gt0 = acc2[mb][nb][half_i * 2 + 0];
                float md1 = acc1[mb][nb][half_i * 2 + 1], gt1 = acc2[mb][nb][half_i * 2 + 1];
                float h0 = md0 / (1.f + __expf(-md0)) * gt0;
                float h1 = md1 / (1.f + __expf(-md1)) * gt1;
                *reinterpret_cast<ushort2*>(&H[(size_t)m * FF + n]) =
                    make_ushort2(__half_as_ushort(__float2half(h0)),
                                 __half_as_ushort(__float2half(h1)));
            }
        }
    }
}

// ============================================================================
// GEMM2: C = A @ B^T ; A:[M,K] fp16, B:[N,K] fp16.
// 128x128x32 CTA tile, 3-stage cp.async pipeline, 8 warps 2(m)x4(n), warp m64xn32.
// ============================================================================
#define GSTG 16384   // A(8K) B(8K)
#define GEMM_SMEM (3 * GSTG)

__global__ __launch_bounds__(256)
void mma_gemm(const __half* __restrict__ A_g, const __half* __restrict__ B_g,
              float* __restrict__ Cg, int M, int N, int K,
              long long strA, long long strB, long long strC)
{
    extern __shared__ char smem[];
    const uint32_t sb = smem_u32(smem);
    const int tid = threadIdx.x, wid = tid >> 5, lane = tid & 31;
    const int wm = wid >> 2, wn = wid & 3;

    const __half* A = A_g + (long long)blockIdx.z * strA;
    const __half* B = B_g + (long long)blockIdx.z * strB;
    float* C = Cg + (long long)blockIdx.z * strC;

    const int rowA0 = blockIdx.y * 128;
    const int colB0 = blockIdx.x * 128;

    float acc[4][4][4];
    #pragma unroll
    for (int i = 0; i < 4; i++)
        #pragma unroll
        for (int j = 0; j < 4; j++)
            #pragma unroll
            for (int k = 0; k < 4; k++) acc[i][j][k] = 0.f;

    const int nC = K >> 5;

    auto load_stage = [&](int c, int s) {
        const uint32_t base = sb + s * GSTG;
        const int kc = c << 5;
        #pragma unroll
        for (int i = 0; i < 2; i++) {
            const int idx = tid + (i << 8);
            const int row = idx >> 2, ch = idx & 3;
            const uint32_t o = tileoff(row, ch);
            CP_ASYNC(base + o,        A + (size_t)(rowA0 + row) * K + kc + ch * 8);
            CP_ASYNC(base + 8192 + o, B + (size_t)(colB0 + row) * K + kc + ch * 8);
        }
        CP_COMMIT();
    };

    load_stage(0, 0);
    load_stage(1, 1);

    int s = 0;
    for (int c = 0; c < nC; c++) {
        if (c + 2 < nC) {
            int s2 = s + 2; if (s2 >= 3) s2 -= 3;
            load_stage(c + 2, s2);
            CP_WAIT2();
        } else if (c + 1 < nC) CP_WAIT1();
        else                   CP_WAIT0();
        __syncthreads();

        const uint32_t tb = sb + s * GSTG;

        #pragma unroll
        for (int ks = 0; ks < 2; ks++) {
            uint32_t ah[4][4], bh[4][2];
            const int ch = ks * 2 + (lane >> 4);
            #pragma unroll
            for (int mb = 0; mb < 4; mb++) {
                const int row = wm * 64 + mb * 16 + (lane & 15);
                LDSM4(ah[mb], tb + tileoff(row, ch));
            }
            #pragma unroll
            for (int nb16 = 0; nb16 < 2; nb16++) {
                const int row = wn * 32 + nb16 * 16 + (lane & 15);
                uint32_t r[4];
                LDSM4(r, tb + 8192 + tileoff(row, ch));
                bh[nb16 * 2][0] = r[0]; bh[nb16 * 2][1] = r[2];
                bh[nb16 * 2 + 1][0] = r[1]; bh[nb16 * 2 + 1][1] = r[3];
            }
            #pragma unroll
            for (int mb = 0; mb < 4; mb++)
                #pragma unroll
                for (int nb = 0; nb < 4; nb++)
                    MMA(acc[mb][nb], ah[mb], bh[nb]);
        }
        __syncthreads();
        if (++s == 3) s = 0;
    }

    #pragma unroll
    for (int mb = 0; mb < 4; mb++) {
        const int m = rowA0 + wm * 64 + mb * 16 + (lane >> 2);
        #pragma unroll
        for (int nb = 0; nb < 4; nb++) {
            const int n = colB0 + wn * 32 + nb * 8 + (lane & 3) * 2;
            *reinterpret_cast<float2*>(&C[(size_t)m * N + n]) =
                make_float2(acc[mb][nb][0], acc[mb][nb][1]);
            *reinterpret_cast<float2*>(&C[(size_t)(m + 8) * N + n]) =
                make_float2(acc[mb][nb][2], acc[mb][nb][3]);
        }
    }
}

// ------------------------------ conversion kernels --------------------------
__global__ __launch_bounds__(256)
void convert_f16_kernel(const float* __restrict__ in, __half* __restrict__ out, size_t n4)
{
    size_t i = (size_t)blockIdx.x * blockDim.x + threadIdx.x;
    if (i >= n4) return;
    float4 v = reinterpret_cast<const float4*>(in)[i];
    reinterpret_cast<ushort4*>(out)[i] =
        make_ushort4(__half_as_ushort(__float2half(v.x)), __half_as_ushort(__float2half(v.y)),
                     __half_as_ushort(__float2half(v.z)), __half_as_ushort(__float2half(v.w)));
}

// w [e][K][N] fp32 -> wT [e][N][K] fp16 (32x32 tiles)
__global__ __launch_bounds__(256)
void transpose_h_kernel(const float* __restrict__ w, __half* __restrict__ wT, int K, int N)
{
    __shared__ float t[32][33];
    const int e = blockIdx.z;
    const int n0 = blockIdx.x * 32, k0 = blockIdx.y * 32;
    const int tx = threadIdx.x, ty = threadIdx.y;   // (32, 8)
    const float* we = w + (size_t)e * K * N;
    #pragma unroll
    for (int j = 0; j < 4; j++)
        t[ty + 8 * j][tx] = we[(size_t)(k0 + ty + 8 * j) * N + n0 + tx];
    __syncthreads();
    __half* wo = wT + (size_t)e * N * K;
    #pragma unroll
    for (int j = 0; j < 4; j++)
        wo[(size_t)(n0 + ty + 8 * j) * K + k0 + tx] = __float2half(t[tx][ty + 8 * j]);
}

// ------------------------------ launch --------------------------------------
extern "C" void kernel_launch(void* const* d_in, const int* in_sizes, int n_in,
                              void* d_out, int out_size)
{
    const float* x    = (const float*)d_in[0];
    const float* win  = (const float*)d_in[1];
    const float* wsw  = (const float*)d_in[2];
    const float* wout = (const float*)d_in[3];
    float* out = (float*)d_out;

    __half *xh, *w1h, *w2h, *w3h, *h;
    cudaGetSymbolAddress((void**)&xh, g_xh);
    cudaGetSymbolAddress((void**)&w1h, g_w1h);  cudaGetSymbolAddress((void**)&w2h, g_w2h);
    cudaGetSymbolAddress((void**)&w3h, g_w3h);
    cudaGetSymbolAddress((void**)&h, g_h);

    cudaFuncSetAttribute(fused_gemm1_swiglu, cudaFuncAttributeMaxDynamicSharedMemorySize, FUSED_SMEM);
    cudaFuncSetAttribute(mma_gemm, cudaFuncAttributeMaxDynamicSharedMemorySize, GEMM_SMEM);

    // 1) convert x to fp16
    {
        size_t n4 = (size_t)NE * GG * DD / 4;
        convert_f16_kernel<<<(unsigned)((n4 + 255) / 256), 256>>>(x, xh, n4);
    }
    // 2) transpose weights to [N,K] fp16
    {
        dim3 blk(32, 8);
        transpose_h_kernel<<<dim3(FF / 32, DD / 32, NE), blk>>>(win,  w1h, DD, FF);
        transpose_h_kernel<<<dim3(FF / 32, DD / 32, NE), blk>>>(wsw,  w2h, DD, FF);
        transpose_h_kernel<<<dim3(DD / 32, FF / 32, NE), blk>>>(wout, w3h, FF, DD);
    }
    // 3) fused GEMM1 pair + SwiGLU -> hidden fp16
    {
        dim3 grid(FF / 64, GG / 128, NE);
        fused_gemm1_swiglu<<<grid, 256, FUSED_SMEM>>>(xh, w1h, w2h, h);
    }
    // 4) GEMM2: [G,F] @ [D,F]^T -> [G,D]
    {
        dim3 grid(DD / 128, GG / 128, NE);
        mma_gemm<<<grid, 256, GEMM_SMEM>>>(h, w3h, out, GG, DD, FF,
                                           (long long)GG * FF, (long long)FF * DD, (long long)GG * DD);
    }
}